// round 4
// baseline (speedup 1.0000x reference)
#include <cuda_runtime.h>
#include <cuda_bf16.h>
#include <math.h>

#define B 64
#define T 512
#define E 256
#define H 200
#define G4 800   // 4*H
#define C 20
#define LN_EPS 1e-5f

// ---------------- scratch (device globals; no allocation) ----------------
__device__ float d_x[(size_t)B * T * E];        // LN'd embeddings [B*T, E]
__device__ float d_g0[(size_t)B * T * G4];      // forward gates_x [B*T, 4H]
__device__ float d_g1[(size_t)B * T * G4];      // backward gates_x
__device__ float d_hf[(size_t)B * T * H];       // forward hidden [B*T, H]
__device__ float d_hb[(size_t)B * T * H];       // backward hidden
__device__ float d_logits[(size_t)B * T * C];   // log-softmax emissions
__device__ float d_loss[B];

// ---------------- 1) embedding + layernorm ----------------
// one block per token, 256 threads (== E)
__global__ void embed_ln_kernel(const int* __restrict__ words,
                                const float* __restrict__ emb,
                                const float* __restrict__ gamma,
                                const float* __restrict__ beta) {
    int tok = blockIdx.x;            // b*T + t
    int e = threadIdx.x;
    int w = words[tok];
    float v = emb[(size_t)w * E + e];

    __shared__ float red[256];
    red[e] = v;
    __syncthreads();
    #pragma unroll
    for (int s = 128; s > 0; s >>= 1) {
        if (e < s) red[e] += red[e + s];
        __syncthreads();
    }
    __shared__ float mu_s;
    if (e == 0) mu_s = red[0] * (1.0f / E);
    __syncthreads();
    float mu = mu_s;
    float d = v - mu;
    red[e] = d * d;
    __syncthreads();
    #pragma unroll
    for (int s = 128; s > 0; s >>= 1) {
        if (e < s) red[e] += red[e + s];
        __syncthreads();
    }
    __shared__ float rs_s;
    if (e == 0) rs_s = rsqrtf(red[0] * (1.0f / E) + LN_EPS);
    __syncthreads();
    d_x[(size_t)tok * E + e] = d * rs_s * gamma[e] + beta[e];
}

// ---------------- 2) input GEMM: gates = x @ w_ih^T + b ----------------
// C[m,n] = sum_k A[m,k] * W[n,k] + bias[n];  M=B*T, N=800, K=256
// Tile: BM=128, BN=64, BK=16, 256 threads, micro-tile 8x4
#define GBM 128
#define GBN 64
#define GBK 16
__global__ void gates_gemm(const float* __restrict__ w_f, const float* __restrict__ b_f,
                           const float* __restrict__ w_b, const float* __restrict__ b_b) {
    int dir = blockIdx.z;
    const float* W = dir ? w_b : w_f;
    const float* bias = dir ? b_b : b_f;
    float* out = dir ? d_g1 : d_g0;

    int m0 = blockIdx.y * GBM;
    int n0 = blockIdx.x * GBN;

    __shared__ float As[GBK][GBM];
    __shared__ float Bs[GBK][GBN];

    int tid = threadIdx.x;
    int tx = tid & 15;      // 0..15 -> n sub-tile
    int ty = tid >> 4;      // 0..15 -> m sub-tile
    int lr = tid >> 2;      // 0..63 loader row
    int lc = (tid & 3) * 4; // 0,4,8,12 loader col (float4)

    float acc[8][4];
    #pragma unroll
    for (int i = 0; i < 8; i++)
        #pragma unroll
        for (int j = 0; j < 4; j++) acc[i][j] = 0.f;

    for (int k0 = 0; k0 < E; k0 += GBK) {
        float4 a0 = *(const float4*)(d_x + (size_t)(m0 + lr) * E + k0 + lc);
        float4 a1 = *(const float4*)(d_x + (size_t)(m0 + lr + 64) * E + k0 + lc);
        int wr = n0 + lr;
        float4 bv = (wr < G4) ? *(const float4*)(W + (size_t)wr * E + k0 + lc)
                              : make_float4(0.f, 0.f, 0.f, 0.f);
        As[lc + 0][lr] = a0.x; As[lc + 1][lr] = a0.y; As[lc + 2][lr] = a0.z; As[lc + 3][lr] = a0.w;
        As[lc + 0][lr + 64] = a1.x; As[lc + 1][lr + 64] = a1.y; As[lc + 2][lr + 64] = a1.z; As[lc + 3][lr + 64] = a1.w;
        Bs[lc + 0][lr] = bv.x; Bs[lc + 1][lr] = bv.y; Bs[lc + 2][lr] = bv.z; Bs[lc + 3][lr] = bv.w;
        __syncthreads();

        #pragma unroll
        for (int kk = 0; kk < GBK; kk++) {
            float av[8], bw[4];
            #pragma unroll
            for (int i = 0; i < 8; i++) av[i] = As[kk][ty * 8 + i];
            #pragma unroll
            for (int j = 0; j < 4; j++) bw[j] = Bs[kk][tx * 4 + j];
            #pragma unroll
            for (int i = 0; i < 8; i++)
                #pragma unroll
                for (int j = 0; j < 4; j++) acc[i][j] += av[i] * bw[j];
        }
        __syncthreads();
    }

    #pragma unroll
    for (int i = 0; i < 8; i++) {
        int m = m0 + ty * 8 + i;
        #pragma unroll
        for (int j = 0; j < 4; j++) {
            int n = n0 + tx * 4 + j;
            if (n < G4) out[(size_t)m * G4 + n] = acc[i][j] + bias[n];
        }
    }
}

// ---------------- 3) LSTM recurrent scan ----------------
// grid (B/2, 2): block handles batches (2p, 2p+1) for direction blockIdx.y.
// 224 threads; thread j < H owns hidden unit j (gate rows j, H+j, 2H+j, 3H+j),
// cell state in registers, h double-buffered in shared (one sync per step).
__global__ void lstm_kernel(const float* __restrict__ whf,
                            const float* __restrict__ whb,
                            const int* __restrict__ seq_len) {
    int p = blockIdx.x;
    int dir = blockIdx.y;
    int b0 = 2 * p, b1 = b0 + 1;
    const float* Wh = dir ? whb : whf;
    const float* gates = dir ? d_g1 : d_g0;
    float* hs = dir ? d_hb : d_hf;
    int j = threadIdx.x;

    __shared__ __align__(16) float hsh[2][2][H];
    if (j < H) { hsh[0][0][j] = 0.f; hsh[0][1][j] = 0.f; }
    __syncthreads();

    float c0 = 0.f, c1 = 0.f;
    int L0 = seq_len[b0], L1 = seq_len[b1];

    const float4* Wi = (const float4*)(Wh + (size_t)j * H);
    const float4* Wf = (const float4*)(Wh + (size_t)(H + j) * H);
    const float4* Wg = (const float4*)(Wh + (size_t)(2 * H + j) * H);
    const float4* Wo = (const float4*)(Wh + (size_t)(3 * H + j) * H);

    for (int s = 0; s < T; s++) {
        int t = dir ? (T - 1 - s) : s;
        int cur = s & 1, nxt = cur ^ 1;
        if (j < H) {
            const float* gp0 = gates + (size_t)(b0 * T + t) * G4;
            const float* gp1 = gates + (size_t)(b1 * T + t) * G4;
            float ai0 = gp0[j], af0 = gp0[H + j], ag0 = gp0[2 * H + j], ao0 = gp0[3 * H + j];
            float ai1 = gp1[j], af1 = gp1[H + j], ag1 = gp1[2 * H + j], ao1 = gp1[3 * H + j];

            const float4* h0p = (const float4*)hsh[cur][0];
            const float4* h1p = (const float4*)hsh[cur][1];
            #pragma unroll 5
            for (int k4 = 0; k4 < H / 4; k4++) {
                float4 wi = Wi[k4], wf = Wf[k4], wg = Wg[k4], wo = Wo[k4];
                float4 h0 = h0p[k4], h1 = h1p[k4];
                ai0 += wi.x * h0.x + wi.y * h0.y + wi.z * h0.z + wi.w * h0.w;
                af0 += wf.x * h0.x + wf.y * h0.y + wf.z * h0.z + wf.w * h0.w;
                ag0 += wg.x * h0.x + wg.y * h0.y + wg.z * h0.z + wg.w * h0.w;
                ao0 += wo.x * h0.x + wo.y * h0.y + wo.z * h0.z + wo.w * h0.w;
                ai1 += wi.x * h1.x + wi.y * h1.y + wi.z * h1.z + wi.w * h1.w;
                af1 += wf.x * h1.x + wf.y * h1.y + wf.z * h1.z + wf.w * h1.w;
                ag1 += wg.x * h1.x + wg.y * h1.y + wg.z * h1.z + wg.w * h1.w;
                ao1 += wo.x * h1.x + wo.y * h1.y + wo.z * h1.z + wo.w * h1.w;
            }

            float i0 = 1.f / (1.f + expf(-ai0));
            float f0 = 1.f / (1.f + expf(-af0));
            float o0 = 1.f / (1.f + expf(-ao0));
            float cn0 = f0 * c0 + i0 * tanhf(ag0);
            float hn0 = o0 * tanhf(cn0);
            bool m0 = (t < L0);
            float hp0 = hsh[cur][0][j];
            float hv0 = m0 ? hn0 : hp0;
            c0 = m0 ? cn0 : c0;
            hsh[nxt][0][j] = hv0;
            hs[(size_t)(b0 * T + t) * H + j] = hv0;

            float i1 = 1.f / (1.f + expf(-ai1));
            float f1 = 1.f / (1.f + expf(-af1));
            float o1 = 1.f / (1.f + expf(-ao1));
            float cn1 = f1 * c1 + i1 * tanhf(ag1);
            float hn1 = o1 * tanhf(cn1);
            bool m1 = (t < L1);
            float hp1 = hsh[cur][1][j];
            float hv1 = m1 ? hn1 : hp1;
            c1 = m1 ? cn1 : c1;
            hsh[nxt][1][j] = hv1;
            hs[(size_t)(b1 * T + t) * H + j] = hv1;
        }
        __syncthreads();
    }
}

// ---------------- 4) FC + log-softmax ----------------
// one block per token, 64 threads
__global__ void fc_ls_kernel(const float* __restrict__ fcw, const float* __restrict__ fcb) {
    int tok = blockIdx.x;
    __shared__ float sh[2 * H];
    __shared__ float feats[C];
    __shared__ float lse_s;

    for (int i = threadIdx.x; i < H; i += blockDim.x) {
        sh[i] = d_hf[(size_t)tok * H + i];
        sh[H + i] = d_hb[(size_t)tok * H + i];
    }
    __syncthreads();

    if (threadIdx.x < C) {
        int c = threadIdx.x;
        float a = fcb[c];
        const float* w = fcw + (size_t)c * 2 * H;
        #pragma unroll 8
        for (int k = 0; k < 2 * H; k++) a += sh[k] * w[k];
        feats[c] = a;
    }
    __syncthreads();
    if (threadIdx.x == 0) {
        float m = -1e30f;
        #pragma unroll
        for (int c = 0; c < C; c++) m = fmaxf(m, feats[c]);
        float ssum = 0.f;
        #pragma unroll
        for (int c = 0; c < C; c++) ssum += expf(feats[c] - m);
        lse_s = m + logf(ssum);
    }
    __syncthreads();
    if (threadIdx.x < C)
        d_logits[(size_t)tok * C + threadIdx.x] = feats[threadIdx.x] - lse_s;
}

// ---------------- 5) CRF NLL (one warp per batch) ----------------
__global__ void crf_kernel(const int* __restrict__ target,
                           const int* __restrict__ seq_len,
                           const float* __restrict__ trans,
                           const float* __restrict__ sv,
                           const float* __restrict__ ev) {
    int b = blockIdx.x;
    int tid = threadIdx.x;
    __shared__ float tr[C * C];
    __shared__ float alpha[C];

    for (int i = tid; i < C * C; i += 32) tr[i] = trans[i];
    int L = seq_len[b];
    const int* tgt = target + (size_t)b * T;
    const float* lg = d_logits + (size_t)b * T * C;

    // gold score pieces (parallel over t, warp-reduced)
    float acc = 0.f;
    for (int t = tid; t < L; t += 32) acc += lg[(size_t)t * C + tgt[t]];
    for (int t = 1 + tid; t < L; t += 32) acc += trans[tgt[t - 1] * C + tgt[t]];
    #pragma unroll
    for (int o = 16; o > 0; o >>= 1) acc += __shfl_down_sync(0xffffffffu, acc, o);

    __syncwarp();
    if (tid < C) alpha[tid] = sv[tid] + lg[tid];
    __syncwarp();

    for (int t = 1; t < L; t++) {
        float na = 0.f;
        if (tid < C) {
            float m = -1e30f;
            #pragma unroll
            for (int c1 = 0; c1 < C; c1++) m = fmaxf(m, alpha[c1] + tr[c1 * C + tid]);
            float ssum = 0.f;
            #pragma unroll
            for (int c1 = 0; c1 < C; c1++) ssum += expf(alpha[c1] + tr[c1 * C + tid] - m);
            na = m + logf(ssum) + lg[(size_t)t * C + tid];
        }
        __syncwarp();
        if (tid < C) alpha[tid] = na;
        __syncwarp();
    }

    if (tid == 0) {
        float m = -1e30f;
        #pragma unroll
        for (int c = 0; c < C; c++) m = fmaxf(m, alpha[c] + ev[c]);
        float ssum = 0.f;
        #pragma unroll
        for (int c = 0; c < C; c++) ssum += expf(alpha[c] + ev[c] - m);
        float logZ = m + logf(ssum);
        float gold = acc + sv[tgt[0]] + ev[tgt[L - 1]];
        d_loss[b] = logZ - gold;
    }
}

// ---------------- 6) mean ----------------
__global__ void mean_kernel(float* __restrict__ out) {
    int tid = threadIdx.x;
    __shared__ float red[B];
    red[tid] = d_loss[tid];
    __syncthreads();
    #pragma unroll
    for (int s = 32; s > 0; s >>= 1) {
        if (tid < s) red[tid] += red[tid + s];
        __syncthreads();
    }
    if (tid == 0) out[0] = red[0] * (1.0f / B);
}

// ---------------- launch ----------------
extern "C" void kernel_launch(void* const* d_in, const int* in_sizes, int n_in,
                              void* d_out, int out_size) {
    const int* words    = (const int*)d_in[0];
    const int* seq_len  = (const int*)d_in[1];
    const int* target   = (const int*)d_in[2];
    const float* embed  = (const float*)d_in[3];
    const float* gamma  = (const float*)d_in[4];
    const float* beta   = (const float*)d_in[5];
    const float* wihf   = (const float*)d_in[6];
    const float* whhf   = (const float*)d_in[7];
    const float* bf     = (const float*)d_in[8];
    const float* wihb   = (const float*)d_in[9];
    const float* whhb   = (const float*)d_in[10];
    const float* bb     = (const float*)d_in[11];
    const float* fcw    = (const float*)d_in[12];
    const float* fcb    = (const float*)d_in[13];
    const float* trans  = (const float*)d_in[14];
    const float* sv     = (const float*)d_in[15];
    const float* ev     = (const float*)d_in[16];
    float* out = (float*)d_out;

    embed_ln_kernel<<<B * T, 256>>>(words, embed, gamma, beta);

    dim3 ggrid((G4 + GBN - 1) / GBN, (B * T) / GBM, 2);
    gates_gemm<<<ggrid, 256>>>(wihf, bf, wihb, bb);

    lstm_kernel<<<dim3(B / 2, 2), 224>>>(whhf, whhb, seq_len);

    fc_ls_kernel<<<B * T, 64>>>(fcw, fcb);

    crf_kernel<<<B, 32>>>(target, seq_len, trans, sv, ev);

    mean_kernel<<<1, B>>>(out);
}

// round 5
// speedup vs baseline: 1.7882x; 1.7882x over previous
#include <cuda_runtime.h>
#include <cuda_bf16.h>
#include <math.h>

#define B 64
#define T 512
#define E 256
#define H 200
#define G4 800   // 4*H
#define C 20
#define LN_EPS 1e-5f

// ---------------- scratch (device globals; no allocation) ----------------
__device__ float d_x[(size_t)B * T * E];        // LN'd embeddings [B*T, E]
__device__ float d_g0[(size_t)B * T * G4];      // forward gates_x [B*T, 4H]
__device__ float d_g1[(size_t)B * T * G4];      // backward gates_x
__device__ float d_hf[(size_t)B * T * H];       // forward hidden [B*T, H]
__device__ float d_hb[(size_t)B * T * H];       // backward hidden
__device__ float d_logits[(size_t)B * T * C];   // log-softmax emissions
__device__ float d_loss[B];
__device__ float d_wt[2 * H * G4];              // transposed w_hh: [dir][k][j*4+q]

__device__ __forceinline__ float fsigm(float x) {
    return __fdividef(1.f, 1.f + __expf(-x));
}
__device__ __forceinline__ float ftanh(float x) {
    return __fdividef(2.f, 1.f + __expf(-2.f * x)) - 1.f;
}

// ---------------- 0) transpose w_hh into unit-major float4 layout ----------------
// d_wt[dir][k][j*4+q] = whh_dir[(q*H + j)*H + k]
__global__ void transpose_whh(const float* __restrict__ whf,
                              const float* __restrict__ whb) {
    int idx = blockIdx.x * blockDim.x + threadIdx.x;
    if (idx >= 2 * H * G4) return;
    int dir = idx / (H * G4);
    int r = idx % (H * G4);
    int k = r / G4;
    int g = r % G4;
    int j = g >> 2, q = g & 3;
    const float* W = dir ? whb : whf;
    d_wt[idx] = W[(size_t)(q * H + j) * H + k];
}

// ---------------- 1) embedding + layernorm (single-pass, shuffle reduce) ----------------
__global__ void embed_ln_kernel(const int* __restrict__ words,
                                const float* __restrict__ emb,
                                const float* __restrict__ gamma,
                                const float* __restrict__ beta) {
    int tok = blockIdx.x;
    int e = threadIdx.x;
    int lane = e & 31, w = e >> 5;
    int wd = words[tok];
    float v = emb[(size_t)wd * E + e];

    float s1 = v, s2 = v * v;
    #pragma unroll
    for (int o = 16; o > 0; o >>= 1) {
        s1 += __shfl_down_sync(0xffffffffu, s1, o);
        s2 += __shfl_down_sync(0xffffffffu, s2, o);
    }
    __shared__ float a1[8], a2[8];
    __shared__ float mu_s, rs_s;
    if (lane == 0) { a1[w] = s1; a2[w] = s2; }
    __syncthreads();
    if (e == 0) {
        float t1 = 0.f, t2 = 0.f;
        #pragma unroll
        for (int i = 0; i < 8; i++) { t1 += a1[i]; t2 += a2[i]; }
        float mu = t1 * (1.0f / E);
        float var = t2 * (1.0f / E) - mu * mu;
        mu_s = mu;
        rs_s = rsqrtf(var + LN_EPS);
    }
    __syncthreads();
    d_x[(size_t)tok * E + e] = (v - mu_s) * rs_s * gamma[e] + beta[e];
}

// ---------------- 2) input GEMM: gates = x @ w_ih^T + b ----------------
#define GBM 128
#define GBN 64
#define GBK 16
__global__ void gates_gemm(const float* __restrict__ w_f, const float* __restrict__ b_f,
                           const float* __restrict__ w_b, const float* __restrict__ b_b) {
    int dir = blockIdx.z;
    const float* W = dir ? w_b : w_f;
    const float* bias = dir ? b_b : b_f;
    float* out = dir ? d_g1 : d_g0;

    int m0 = blockIdx.y * GBM;
    int n0 = blockIdx.x * GBN;

    __shared__ float As[GBK][GBM];
    __shared__ float Bs[GBK][GBN];

    int tid = threadIdx.x;
    int tx = tid & 15;
    int ty = tid >> 4;
    int lr = tid >> 2;
    int lc = (tid & 3) * 4;

    float acc[8][4];
    #pragma unroll
    for (int i = 0; i < 8; i++)
        #pragma unroll
        for (int j = 0; j < 4; j++) acc[i][j] = 0.f;

    for (int k0 = 0; k0 < E; k0 += GBK) {
        float4 a0 = *(const float4*)(d_x + (size_t)(m0 + lr) * E + k0 + lc);
        float4 a1 = *(const float4*)(d_x + (size_t)(m0 + lr + 64) * E + k0 + lc);
        int wr = n0 + lr;
        float4 bv = (wr < G4) ? *(const float4*)(W + (size_t)wr * E + k0 + lc)
                              : make_float4(0.f, 0.f, 0.f, 0.f);
        As[lc + 0][lr] = a0.x; As[lc + 1][lr] = a0.y; As[lc + 2][lr] = a0.z; As[lc + 3][lr] = a0.w;
        As[lc + 0][lr + 64] = a1.x; As[lc + 1][lr + 64] = a1.y; As[lc + 2][lr + 64] = a1.z; As[lc + 3][lr + 64] = a1.w;
        Bs[lc + 0][lr] = bv.x; Bs[lc + 1][lr] = bv.y; Bs[lc + 2][lr] = bv.z; Bs[lc + 3][lr] = bv.w;
        __syncthreads();

        #pragma unroll
        for (int kk = 0; kk < GBK; kk++) {
            float av[8], bw[4];
            #pragma unroll
            for (int i = 0; i < 8; i++) av[i] = As[kk][ty * 8 + i];
            #pragma unroll
            for (int j = 0; j < 4; j++) bw[j] = Bs[kk][tx * 4 + j];
            #pragma unroll
            for (int i = 0; i < 8; i++)
                #pragma unroll
                for (int j = 0; j < 4; j++) acc[i][j] += av[i] * bw[j];
        }
        __syncthreads();
    }

    #pragma unroll
    for (int i = 0; i < 8; i++) {
        int m = m0 + ty * 8 + i;
        #pragma unroll
        for (int j = 0; j < 4; j++) {
            int n = n0 + tx * 4 + j;
            if (n < G4) out[(size_t)m * G4 + n] = acc[i][j] + bias[n];
        }
    }
}

// ---------------- 3) LSTM recurrent scan (coalesced unit-major weights) ----------------
// grid (B/2, 2): block handles 2 batches for direction blockIdx.y.
// Thread j owns hidden unit j; Wt[k][j] float4 = (i,f,g,o) weights of unit j
// for input k -> lanes read contiguous 16B chunks (fully coalesced).
__global__ void lstm_kernel(const int* __restrict__ seq_len) {
    int p = blockIdx.x;
    int dir = blockIdx.y;
    int b0 = 2 * p, b1 = b0 + 1;
    const float4* Wt = (const float4*)(d_wt + (size_t)dir * H * G4);
    const float* gates = dir ? d_g1 : d_g0;
    float* hs = dir ? d_hb : d_hf;
    int j = threadIdx.x;

    __shared__ __align__(16) float2 hsh[2][H];
    if (j < H) hsh[0][j] = make_float2(0.f, 0.f);
    __syncthreads();

    float c0 = 0.f, c1 = 0.f;
    int L0 = seq_len[b0], L1 = seq_len[b1];

    for (int s = 0; s < T; s++) {
        int t = dir ? (T - 1 - s) : s;
        int cur = s & 1, nxt = cur ^ 1;
        if (j < H) {
            const float* gp0 = gates + (size_t)(b0 * T + t) * G4;
            const float* gp1 = gates + (size_t)(b1 * T + t) * G4;
            // issue gate-preact loads early; consumed only after the k-loop
            float gi0 = gp0[j], gf0 = gp0[H + j], gg0 = gp0[2 * H + j], go0 = gp0[3 * H + j];
            float gi1 = gp1[j], gf1 = gp1[H + j], gg1 = gp1[2 * H + j], go1 = gp1[3 * H + j];

            float ai0 = 0.f, af0 = 0.f, ag0 = 0.f, ao0 = 0.f;
            float ai1 = 0.f, af1 = 0.f, ag1 = 0.f, ao1 = 0.f;

            const float4* wp = Wt + j;
            const float2* hp = hsh[cur];
            #pragma unroll 4
            for (int k = 0; k < H; k++) {
                float4 w = wp[k * (G4 / 4)];
                float2 h = hp[k];
                ai0 += w.x * h.x; af0 += w.y * h.x; ag0 += w.z * h.x; ao0 += w.w * h.x;
                ai1 += w.x * h.y; af1 += w.y * h.y; ag1 += w.z * h.y; ao1 += w.w * h.y;
            }

            float2 hprev = hsh[cur][j];

            float i0 = fsigm(ai0 + gi0);
            float f0 = fsigm(af0 + gf0);
            float o0 = fsigm(ao0 + go0);
            float cn0 = f0 * c0 + i0 * ftanh(ag0 + gg0);
            float hn0 = o0 * ftanh(cn0);
            bool m0 = (t < L0);
            float hv0 = m0 ? hn0 : hprev.x;
            c0 = m0 ? cn0 : c0;

            float i1 = fsigm(ai1 + gi1);
            float f1 = fsigm(af1 + gf1);
            float o1 = fsigm(ao1 + go1);
            float cn1 = f1 * c1 + i1 * ftanh(ag1 + gg1);
            float hn1 = o1 * ftanh(cn1);
            bool m1 = (t < L1);
            float hv1 = m1 ? hn1 : hprev.y;
            c1 = m1 ? cn1 : c1;

            hsh[nxt][j] = make_float2(hv0, hv1);
            hs[(size_t)(b0 * T + t) * H + j] = hv0;
            hs[(size_t)(b1 * T + t) * H + j] = hv1;
        }
        __syncthreads();
    }
}

// ---------------- 4) FC + log-softmax ----------------
// block = 8 tokens x 20 classes = 160 threads; weights transposed in shared.
#define FTOK 8
__global__ void fc_ls_kernel(const float* __restrict__ fcw, const float* __restrict__ fcb) {
    __shared__ float shw[2 * H * C];       // shw[k*C + c]  (k uniform per instr -> conflict-free)
    __shared__ float shh[FTOK][2 * H];     // concat [hf|hb] per token
    __shared__ float sfeat[FTOK][C];
    __shared__ float slse[FTOK];

    int tid = threadIdx.x;
    int tt = tid / C;         // token within block
    int c = tid % C;          // class
    int tok0 = blockIdx.x * FTOK;

    // stage weights transposed: shw[k][c] = fcw[c*400 + k]
    for (int idx = tid; idx < 2 * H * C; idx += FTOK * C) {
        int cc = idx / (2 * H);
        int k = idx % (2 * H);
        shw[k * C + cc] = fcw[idx];
    }
    // stage hidden states
    for (int idx = tid; idx < FTOK * 2 * H; idx += FTOK * C) {
        int t = idx / (2 * H);
        int k = idx % (2 * H);
        size_t tok = tok0 + t;
        shh[t][k] = (k < H) ? d_hf[tok * H + k] : d_hb[tok * H + (k - H)];
    }
    __syncthreads();

    float acc = fcb[c];
    const float* hrow = shh[tt];
    #pragma unroll 8
    for (int k = 0; k < 2 * H; k++)
        acc += hrow[k] * shw[k * C + c];
    sfeat[tt][c] = acc;
    __syncthreads();

    if (c == 0) {
        float m = sfeat[tt][0];
        #pragma unroll
        for (int i = 1; i < C; i++) m = fmaxf(m, sfeat[tt][i]);
        float ssum = 0.f;
        #pragma unroll
        for (int i = 0; i < C; i++) ssum += __expf(sfeat[tt][i] - m);
        slse[tt] = m + __logf(ssum);
    }
    __syncthreads();
    d_logits[(size_t)(tok0 + tt) * C + c] = acc - slse[tt];
}

// ---------------- 5) CRF NLL (one warp per batch) ----------------
__global__ void crf_kernel(const int* __restrict__ target,
                           const int* __restrict__ seq_len,
                           const float* __restrict__ trans,
                           const float* __restrict__ sv,
                           const float* __restrict__ ev) {
    int b = blockIdx.x;
    int tid = threadIdx.x;
    __shared__ float tr[C * C];
    __shared__ float alpha[C];

    for (int i = tid; i < C * C; i += 32) tr[i] = trans[i];
    int L = seq_len[b];
    const int* tgt = target + (size_t)b * T;
    const float* lg = d_logits + (size_t)b * T * C;

    // gold score (parallel over t, warp-reduced)
    float acc = 0.f;
    for (int t = tid; t < L; t += 32) acc += lg[(size_t)t * C + tgt[t]];
    for (int t = 1 + tid; t < L; t += 32) acc += trans[tgt[t - 1] * C + tgt[t]];
    #pragma unroll
    for (int o = 16; o > 0; o >>= 1) acc += __shfl_down_sync(0xffffffffu, acc, o);

    __syncwarp();
    if (tid < C) alpha[tid] = sv[tid] + lg[tid];
    __syncwarp();

    // register-resident transition column for this lane's destination tag
    float trcol[C];
    if (tid < C) {
        #pragma unroll
        for (int c1 = 0; c1 < C; c1++) trcol[c1] = tr[c1 * C + tid];
    }

    for (int t = 1; t < L; t++) {
        float na = 0.f;
        if (tid < C) {
            float v[C];
            #pragma unroll
            for (int c1 = 0; c1 < C; c1++) v[c1] = alpha[c1] + trcol[c1];
            // tree max
            float mx[C];
            #pragma unroll
            for (int c1 = 0; c1 < C; c1++) mx[c1] = v[c1];
            #pragma unroll
            for (int st = 1; st < C; st *= 2)
                #pragma unroll
                for (int i = 0; i + st < C; i += 2 * st) mx[i] = fmaxf(mx[i], mx[i + st]);
            float m = mx[0];
            #pragma unroll
            for (int c1 = 0; c1 < C; c1++) v[c1] = __expf(v[c1] - m);
            #pragma unroll
            for (int st = 1; st < C; st *= 2)
                #pragma unroll
                for (int i = 0; i + st < C; i += 2 * st) v[i] += v[i + st];
            na = m + __logf(v[0]) + lg[(size_t)t * C + tid];
        }
        __syncwarp();
        if (tid < C) alpha[tid] = na;
        __syncwarp();
    }

    if (tid == 0) {
        float m = -1e30f;
        #pragma unroll
        for (int c = 0; c < C; c++) m = fmaxf(m, alpha[c] + ev[c]);
        float ssum = 0.f;
        #pragma unroll
        for (int c = 0; c < C; c++) ssum += __expf(alpha[c] + ev[c] - m);
        float logZ = m + __logf(ssum);
        float gold = acc + sv[tgt[0]] + ev[tgt[L - 1]];
        d_loss[b] = logZ - gold;
    }
}

// ---------------- 6) mean ----------------
__global__ void mean_kernel(float* __restrict__ out) {
    int tid = threadIdx.x;
    __shared__ float red[B];
    red[tid] = d_loss[tid];
    __syncthreads();
    #pragma unroll
    for (int s = 32; s > 0; s >>= 1) {
        if (tid < s) red[tid] += red[tid + s];
        __syncthreads();
    }
    if (tid == 0) out[0] = red[0] * (1.0f / B);
}

// ---------------- launch ----------------
extern "C" void kernel_launch(void* const* d_in, const int* in_sizes, int n_in,
                              void* d_out, int out_size) {
    const int* words    = (const int*)d_in[0];
    const int* seq_len  = (const int*)d_in[1];
    const int* target   = (const int*)d_in[2];
    const float* embed  = (const float*)d_in[3];
    const float* gamma  = (const float*)d_in[4];
    const float* beta   = (const float*)d_in[5];
    const float* wihf   = (const float*)d_in[6];
    const float* whhf   = (const float*)d_in[7];
    const float* bf     = (const float*)d_in[8];
    const float* wihb   = (const float*)d_in[9];
    const float* whhb   = (const float*)d_in[10];
    const float* bb     = (const float*)d_in[11];
    const float* fcw    = (const float*)d_in[12];
    const float* fcb    = (const float*)d_in[13];
    const float* trans  = (const float*)d_in[14];
    const float* sv     = (const float*)d_in[15];
    const float* ev     = (const float*)d_in[16];
    float* out = (float*)d_out;

    transpose_whh<<<(2 * H * G4 + 255) / 256, 256>>>(whhf, whhb);

    embed_ln_kernel<<<B * T, 256>>>(words, embed, gamma, beta);

    dim3 ggrid((G4 + GBN - 1) / GBN, (B * T) / GBM, 2);
    gates_gemm<<<ggrid, 256>>>(wihf, bf, wihb, bb);

    lstm_kernel<<<dim3(B / 2, 2), 224>>>(seq_len);

    fc_ls_kernel<<<(B * T) / FTOK, FTOK * C>>>(fcw, fcb);

    crf_kernel<<<B, 32>>>(target, seq_len, trans, sv, ev);

    mean_kernel<<<1, B>>>(out);
}

// round 8
// speedup vs baseline: 2.7407x; 1.5326x over previous
#include <cuda_runtime.h>
#include <cuda_bf16.h>
#include <math.h>
#include <stdint.h>

#define B 64
#define T 512
#define E 256
#define H 200
#define G4 800   // 4*H
#define C 20
#define LN_EPS 1e-5f

// LSTM cluster config
#define UPC 50        // hidden units per CTA (4 CTAs/cluster -> 200)
#define NBATCH 4      // batches per cluster
#define KSTRIDE 201   // float4 stride for weight rows (padded: conflict-free)
#define LSTM_SMEM (UPC * KSTRIDE * 16 + 2 * NBATCH * H * 4)

// ---------------- scratch (device globals; no allocation) ----------------
__device__ float d_x[(size_t)B * T * E];        // LN'd embeddings [B*T, E]
__device__ float d_g0[(size_t)B * T * G4];      // forward gates_x [B*T, 4H]
__device__ float d_g1[(size_t)B * T * G4];      // backward gates_x
__device__ float d_hf[(size_t)B * T * H];       // forward hidden [B*T, H]
__device__ float d_hb[(size_t)B * T * H];       // backward hidden
__device__ float d_logits[(size_t)B * T * C];   // log-softmax emissions
__device__ float d_loss[B];
__device__ float d_wt[2 * H * G4];              // transposed w_hh: [dir][k][j*4+q]

__device__ __forceinline__ float fsigm(float x) {
    return __fdividef(1.f, 1.f + __expf(-x));
}
__device__ __forceinline__ float ftanh(float x) {
    return __fdividef(2.f, 1.f + __expf(-2.f * x)) - 1.f;
}

__device__ __forceinline__ void cluster_sync_() {
    asm volatile("barrier.cluster.arrive.aligned;" ::: "memory");
    asm volatile("barrier.cluster.wait.aligned;" ::: "memory");
}
// store float to the same smem offset in CTA `rank` of the cluster
__device__ __forceinline__ void st_shared_cluster(uint32_t laddr, int rank, float v) {
    uint32_t raddr;
    asm volatile("mapa.shared::cluster.u32 %0, %1, %2;" : "=r"(raddr) : "r"(laddr), "r"(rank));
    asm volatile("st.shared::cluster.f32 [%0], %1;" :: "r"(raddr), "f"(v) : "memory");
}

// ---------------- 0) transpose w_hh into unit-major float4 layout ----------------
// d_wt[dir][k][j*4+q] = whh_dir[(q*H + j)*H + k]
__global__ void transpose_whh(const float* __restrict__ whf,
                              const float* __restrict__ whb) {
    int idx = blockIdx.x * blockDim.x + threadIdx.x;
    if (idx >= 2 * H * G4) return;
    int dir = idx / (H * G4);
    int r = idx % (H * G4);
    int k = r / G4;
    int g = r % G4;
    int j = g >> 2, q = g & 3;
    const float* W = dir ? whb : whf;
    d_wt[idx] = W[(size_t)(q * H + j) * H + k];
}

// ---------------- 1) embedding + layernorm (single-pass, shuffle reduce) ----------------
__global__ void embed_ln_kernel(const int* __restrict__ words,
                                const float* __restrict__ emb,
                                const float* __restrict__ gamma,
                                const float* __restrict__ beta) {
    int tok = blockIdx.x;
    int e = threadIdx.x;
    int lane = e & 31, w = e >> 5;
    int wd = words[tok];
    float v = emb[(size_t)wd * E + e];

    float s1 = v, s2 = v * v;
    #pragma unroll
    for (int o = 16; o > 0; o >>= 1) {
        s1 += __shfl_down_sync(0xffffffffu, s1, o);
        s2 += __shfl_down_sync(0xffffffffu, s2, o);
    }
    __shared__ float a1[8], a2[8];
    __shared__ float mu_s, rs_s;
    if (lane == 0) { a1[w] = s1; a2[w] = s2; }
    __syncthreads();
    if (e == 0) {
        float t1 = 0.f, t2 = 0.f;
        #pragma unroll
        for (int i = 0; i < 8; i++) { t1 += a1[i]; t2 += a2[i]; }
        float mu = t1 * (1.0f / E);
        float var = t2 * (1.0f / E) - mu * mu;
        mu_s = mu;
        rs_s = rsqrtf(var + LN_EPS);
    }
    __syncthreads();
    d_x[(size_t)tok * E + e] = (v - mu_s) * rs_s * gamma[e] + beta[e];
}

// ---------------- 2) input GEMM: gates = x @ w_ih^T + b ----------------
#define GBM 128
#define GBN 64
#define GBK 16
__global__ void gates_gemm(const float* __restrict__ w_f, const float* __restrict__ b_f,
                           const float* __restrict__ w_b, const float* __restrict__ b_b) {
    int dir = blockIdx.z;
    const float* W = dir ? w_b : w_f;
    const float* bias = dir ? b_b : b_f;
    float* out = dir ? d_g1 : d_g0;

    int m0 = blockIdx.y * GBM;
    int n0 = blockIdx.x * GBN;

    __shared__ float As[GBK][GBM];
    __shared__ float Bs[GBK][GBN];

    int tid = threadIdx.x;
    int tx = tid & 15;
    int ty = tid >> 4;
    int lr = tid >> 2;
    int lc = (tid & 3) * 4;

    float acc[8][4];
    #pragma unroll
    for (int i = 0; i < 8; i++)
        #pragma unroll
        for (int j = 0; j < 4; j++) acc[i][j] = 0.f;

    for (int k0 = 0; k0 < E; k0 += GBK) {
        float4 a0 = *(const float4*)(d_x + (size_t)(m0 + lr) * E + k0 + lc);
        float4 a1 = *(const float4*)(d_x + (size_t)(m0 + lr + 64) * E + k0 + lc);
        int wr = n0 + lr;
        float4 bv = (wr < G4) ? *(const float4*)(W + (size_t)wr * E + k0 + lc)
                              : make_float4(0.f, 0.f, 0.f, 0.f);
        As[lc + 0][lr] = a0.x; As[lc + 1][lr] = a0.y; As[lc + 2][lr] = a0.z; As[lc + 3][lr] = a0.w;
        As[lc + 0][lr + 64] = a1.x; As[lc + 1][lr + 64] = a1.y; As[lc + 2][lr + 64] = a1.z; As[lc + 3][lr + 64] = a1.w;
        Bs[lc + 0][lr] = bv.x; Bs[lc + 1][lr] = bv.y; Bs[lc + 2][lr] = bv.z; Bs[lc + 3][lr] = bv.w;
        __syncthreads();

        #pragma unroll
        for (int kk = 0; kk < GBK; kk++) {
            float av[8], bw[4];
            #pragma unroll
            for (int i = 0; i < 8; i++) av[i] = As[kk][ty * 8 + i];
            #pragma unroll
            for (int j = 0; j < 4; j++) bw[j] = Bs[kk][tx * 4 + j];
            #pragma unroll
            for (int i = 0; i < 8; i++)
                #pragma unroll
                for (int j = 0; j < 4; j++) acc[i][j] += av[i] * bw[j];
        }
        __syncthreads();
    }

    #pragma unroll
    for (int i = 0; i < 8; i++) {
        int m = m0 + ty * 8 + i;
        #pragma unroll
        for (int j = 0; j < 4; j++) {
            int n = n0 + tx * 4 + j;
            if (n < G4) out[(size_t)m * G4 + n] = acc[i][j] + bias[n];
        }
    }
}

// ---------------- 3) LSTM: 4-CTA cluster, SMEM-resident weights ----------------
// Grid: 128 CTAs = 32 clusters of 4. Cluster cid handles direction (cid&1) and
// batch group (cid>>1)*4 .. +3. CTA rank owns units [rank*50, rank*50+50).
// Weights live in smem (loaded once); h is replicated per CTA, double-buffered,
// exchanged via DSMEM stores + one cluster barrier per step.
__global__ void __cluster_dims__(4, 1, 1) lstm_cluster_kernel(const int* __restrict__ seq_len) {
    extern __shared__ __align__(16) float4 smem4[];
    float4* wsm = smem4;                                    // [UPC][KSTRIDE] float4
    float* hbuf = (float*)(smem4 + UPC * KSTRIDE);          // [2][NBATCH][H]

    int cid = blockIdx.x >> 2;
    uint32_t rank;
    asm("mov.u32 %0, %%cluster_ctarank;" : "=r"(rank));
    int dir = cid & 1;
    int grp = cid >> 1;
    int tid = threadIdx.x;

    const float* gates = dir ? d_g1 : d_g0;
    float* hs = dir ? d_hb : d_hf;

    // load this CTA's 50-unit weight slice: wsm[jl][k] = d_wt[dir][k][(rank*50+jl)]
    const float4* wsrc = (const float4*)(d_wt + (size_t)dir * H * G4);
    for (int idx = tid; idx < UPC * H; idx += blockDim.x) {
        int k = idx / UPC;
        int jl = idx % UPC;
        wsm[jl * KSTRIDE + k] = wsrc[(size_t)k * (G4 / 4) + rank * UPC + jl];
    }
    // zero h double buffer
    for (int idx = tid; idx < 2 * NBATCH * H; idx += blockDim.x) hbuf[idx] = 0.f;

    int jl = tid >> 2;          // local unit 0..63 (active < UPC)
    int b = tid & 3;            // batch within group
    int jg = rank * UPC + jl;   // global unit
    int bg = grp * NBATCH + b;  // global batch
    bool active = (jl < UPC);
    int L = active ? seq_len[bg] : 0;
    float c = 0.f;

    cluster_sync_();   // weights + zeroed h visible cluster-wide

    for (int s = 0; s < T; s++) {
        int t = dir ? (T - 1 - s) : s;
        int cur = s & 1, nxt = cur ^ 1;
        if (active) {
            const float* gp = gates + ((size_t)bg * T + t) * G4;
            float gi = gp[jg], gf = gp[H + jg], gg = gp[2 * H + jg], go = gp[3 * H + jg];

            const float4* hp = (const float4*)(hbuf + (cur * NBATCH + b) * H);
            const float4* wp = wsm + jl * KSTRIDE;
            float ai = 0.f, af = 0.f, ag = 0.f, ao = 0.f;
            #pragma unroll 5
            for (int k4 = 0; k4 < H / 4; k4++) {
                float4 h4 = hp[k4];
                float4 w0 = wp[4 * k4 + 0];
                float4 w1 = wp[4 * k4 + 1];
                float4 w2 = wp[4 * k4 + 2];
                float4 w3 = wp[4 * k4 + 3];
                ai += w0.x * h4.x; af += w0.y * h4.x; ag += w0.z * h4.x; ao += w0.w * h4.x;
                ai += w1.x * h4.y; af += w1.y * h4.y; ag += w1.z * h4.y; ao += w1.w * h4.y;
                ai += w2.x * h4.z; af += w2.y * h4.z; ag += w2.z * h4.z; ao += w2.w * h4.z;
                ai += w3.x * h4.w; af += w3.y * h4.w; ag += w3.z * h4.w; ao += w3.w * h4.w;
            }

            float i = fsigm(ai + gi);
            float f = fsigm(af + gf);
            float o = fsigm(ao + go);
            float cn = f * c + i * ftanh(ag + gg);
            float hn = o * ftanh(cn);
            bool m = (t < L);
            float hprev = hbuf[(cur * NBATCH + b) * H + jg];
            float hv = m ? hn : hprev;
            c = m ? cn : c;

            // broadcast h[jg] for batch b into every CTA's next buffer
            uint32_t laddr = (uint32_t)__cvta_generic_to_shared(
                &hbuf[(nxt * NBATCH + b) * H + jg]);
            st_shared_cluster(laddr, 0, hv);
            st_shared_cluster(laddr, 1, hv);
            st_shared_cluster(laddr, 2, hv);
            st_shared_cluster(laddr, 3, hv);

            hs[((size_t)bg * T + t) * H + jg] = hv;
        }
        cluster_sync_();
    }
}

// ---------------- 4) FC + log-softmax ----------------
#define FTOK 8
__global__ void fc_ls_kernel(const float* __restrict__ fcw, const float* __restrict__ fcb) {
    __shared__ float shw[2 * H * C];       // shw[k*C + c]
    __shared__ float shh[FTOK][2 * H];
    __shared__ float sfeat[FTOK][C];
    __shared__ float slse[FTOK];

    int tid = threadIdx.x;
    int tt = tid / C;
    int c = tid % C;
    int tok0 = blockIdx.x * FTOK;

    for (int idx = tid; idx < 2 * H * C; idx += FTOK * C) {
        int cc = idx / (2 * H);
        int k = idx % (2 * H);
        shw[k * C + cc] = fcw[idx];
    }
    for (int idx = tid; idx < FTOK * 2 * H; idx += FTOK * C) {
        int t = idx / (2 * H);
        int k = idx % (2 * H);
        size_t tok = tok0 + t;
        shh[t][k] = (k < H) ? d_hf[tok * H + k] : d_hb[tok * H + (k - H)];
    }
    __syncthreads();

    float acc = fcb[c];
    const float* hrow = shh[tt];
    #pragma unroll 8
    for (int k = 0; k < 2 * H; k++)
        acc += hrow[k] * shw[k * C + c];
    sfeat[tt][c] = acc;
    __syncthreads();

    if (c == 0) {
        float m = sfeat[tt][0];
        #pragma unroll
        for (int i = 1; i < C; i++) m = fmaxf(m, sfeat[tt][i]);
        float ssum = 0.f;
        #pragma unroll
        for (int i = 0; i < C; i++) ssum += __expf(sfeat[tt][i] - m);
        slse[tt] = m + __logf(ssum);
    }
    __syncthreads();
    d_logits[(size_t)(tok0 + tt) * C + c] = acc - slse[tt];
}

// ---------------- 5) CRF NLL (one warp per batch) ----------------
__global__ void crf_kernel(const int* __restrict__ target,
                           const int* __restrict__ seq_len,
                           const float* __restrict__ trans,
                           const float* __restrict__ sv,
                           const float* __restrict__ ev) {
    int b = blockIdx.x;
    int tid = threadIdx.x;
    __shared__ float tr[C * C];
    __shared__ float alpha[C];

    for (int i = tid; i < C * C; i += 32) tr[i] = trans[i];
    int L = seq_len[b];
    const int* tgt = target + (size_t)b * T;
    const float* lg = d_logits + (size_t)b * T * C;

    float acc = 0.f;
    for (int t = tid; t < L; t += 32) acc += lg[(size_t)t * C + tgt[t]];
    for (int t = 1 + tid; t < L; t += 32) acc += trans[tgt[t - 1] * C + tgt[t]];
    #pragma unroll
    for (int o = 16; o > 0; o >>= 1) acc += __shfl_down_sync(0xffffffffu, acc, o);

    __syncwarp();
    if (tid < C) alpha[tid] = sv[tid] + lg[tid];
    __syncwarp();

    float trcol[C];
    if (tid < C) {
        #pragma unroll
        for (int c1 = 0; c1 < C; c1++) trcol[c1] = tr[c1 * C + tid];
    }

    for (int t = 1; t < L; t++) {
        float na = 0.f;
        if (tid < C) {
            float v[C];
            #pragma unroll
            for (int c1 = 0; c1 < C; c1++) v[c1] = alpha[c1] + trcol[c1];
            float mx[C];
            #pragma unroll
            for (int c1 = 0; c1 < C; c1++) mx[c1] = v[c1];
            #pragma unroll
            for (int st = 1; st < C; st *= 2)
                #pragma unroll
                for (int i = 0; i + st < C; i += 2 * st) mx[i] = fmaxf(mx[i], mx[i + st]);
            float m = mx[0];
            #pragma unroll
            for (int c1 = 0; c1 < C; c1++) v[c1] = __expf(v[c1] - m);
            #pragma unroll
            for (int st = 1; st < C; st *= 2)
                #pragma unroll
                for (int i = 0; i + st < C; i += 2 * st) v[i] += v[i + st];
            na = m + __logf(v[0]) + lg[(size_t)t * C + tid];
        }
        __syncwarp();
        if (tid < C) alpha[tid] = na;
        __syncwarp();
    }

    if (tid == 0) {
        float m = -1e30f;
        #pragma unroll
        for (int c = 0; c < C; c++) m = fmaxf(m, alpha[c] + ev[c]);
        float ssum = 0.f;
        #pragma unroll
        for (int c = 0; c < C; c++) ssum += __expf(alpha[c] + ev[c] - m);
        float logZ = m + __logf(ssum);
        float gold = acc + sv[tgt[0]] + ev[tgt[L - 1]];
        d_loss[b] = logZ - gold;
    }
}

// ---------------- 6) mean ----------------
__global__ void mean_kernel(float* __restrict__ out) {
    int tid = threadIdx.x;
    __shared__ float red[B];
    red[tid] = d_loss[tid];
    __syncthreads();
    #pragma unroll
    for (int s = 32; s > 0; s >>= 1) {
        if (tid < s) red[tid] += red[tid + s];
        __syncthreads();
    }
    if (tid == 0) out[0] = red[0] * (1.0f / B);
}

// ---------------- launch ----------------
extern "C" void kernel_launch(void* const* d_in, const int* in_sizes, int n_in,
                              void* d_out, int out_size) {
    const int* words    = (const int*)d_in[0];
    const int* seq_len  = (const int*)d_in[1];
    const int* target   = (const int*)d_in[2];
    const float* embed  = (const float*)d_in[3];
    const float* gamma  = (const float*)d_in[4];
    const float* beta   = (const float*)d_in[5];
    const float* wihf   = (const float*)d_in[6];
    const float* whhf   = (const float*)d_in[7];
    const float* bf     = (const float*)d_in[8];
    const float* wihb   = (const float*)d_in[9];
    const float* whhb   = (const float*)d_in[10];
    const float* bb     = (const float*)d_in[11];
    const float* fcw    = (const float*)d_in[12];
    const float* fcb    = (const float*)d_in[13];
    const float* trans  = (const float*)d_in[14];
    const float* sv     = (const float*)d_in[15];
    const float* ev     = (const float*)d_in[16];
    float* out = (float*)d_out;

    cudaFuncSetAttribute(lstm_cluster_kernel,
                         cudaFuncAttributeMaxDynamicSharedMemorySize, LSTM_SMEM);

    transpose_whh<<<(2 * H * G4 + 255) / 256, 256>>>(whhf, whhb);

    embed_ln_kernel<<<B * T, 256>>>(words, embed, gamma, beta);

    dim3 ggrid((G4 + GBN - 1) / GBN, (B * T) / GBM, 2);
    gates_gemm<<<ggrid, 256>>>(wihf, bf, wihb, bb);

    lstm_cluster_kernel<<<128, 256, LSTM_SMEM>>>(seq_len);

    fc_ls_kernel<<<(B * T) / FTOK, FTOK * C>>>(fcw, fcb);

    crf_kernel<<<B, 32>>>(target, seq_len, trans, sv, ev);

    mean_kernel<<<1, B>>>(out);
}

// round 9
// speedup vs baseline: 4.4028x; 1.6065x over previous
#include <cuda_runtime.h>
#include <cuda_bf16.h>
#include <math.h>
#include <stdint.h>

#define B 64
#define T 512
#define E 256
#define H 200
#define G4 800   // 4*H
#define C 20
#define LN_EPS 1e-5f

typedef unsigned long long ull;

// LSTM cluster config
#define UPC 50          // hidden units per CTA (4 CTAs/cluster -> 200)
#define NBATCH 4        // batches per cluster
#define WJSTR 808       // floats per unit weight block (4 gates * 200 k, padded +8)
#define HPAD 232        // floats per batch row in h buffer (padded for banks)
#define LSTM_SMEM (UPC * WJSTR * 4 + 2 * NBATCH * HPAD * 4)   // 161600 + 7424

// GEMM config
#define TBM 128
#define TBN 64
#define TBK 32
#define AS2STR 132      // float2 per k2-row (128 + pad)
#define BS2STR 68       // float2 per k2-row (64 + pad)
#define GEMM_SMEM (2 * (TBK/2) * AS2STR * 8 + 2 * (TBK/2) * BS2STR * 8)  // 51200

// ---------------- scratch (device globals; no allocation) ----------------
__device__ float d_x[(size_t)B * T * E];
__device__ float d_g0[(size_t)B * T * G4];
__device__ float d_g1[(size_t)B * T * G4];
__device__ float d_hf[(size_t)B * T * H];
__device__ float d_hb[(size_t)B * T * H];
__device__ float d_logits[(size_t)B * T * C];
__device__ float d_loss[B];
__device__ float d_wt[2 * H * G4];   // [dir][unit j][gate g][k]

__device__ __forceinline__ float fsigm(float x) {
    return __fdividef(1.f, 1.f + __expf(-x));
}
__device__ __forceinline__ float ftanh(float x) {
    return __fdividef(2.f, 1.f + __expf(-2.f * x)) - 1.f;
}
__device__ __forceinline__ ull ffma2(ull a, ull b, ull c) {
    ull d;
    asm("fma.rn.f32x2 %0, %1, %2, %3;" : "=l"(d) : "l"(a), "l"(b), "l"(c));
    return d;
}
__device__ __forceinline__ float2 uf2(ull u) {
    float2 f;
    f.x = __uint_as_float((unsigned)(u & 0xffffffffu));
    f.y = __uint_as_float((unsigned)(u >> 32));
    return f;
}
__device__ __forceinline__ void cluster_sync_() {
    asm volatile("barrier.cluster.arrive.aligned;" ::: "memory");
    asm volatile("barrier.cluster.wait.aligned;" ::: "memory");
}
__device__ __forceinline__ void st_shared_cluster(uint32_t laddr, int rank, float v) {
    uint32_t raddr;
    asm volatile("mapa.shared::cluster.u32 %0, %1, %2;" : "=r"(raddr) : "r"(laddr), "r"(rank));
    asm volatile("st.shared::cluster.f32 [%0], %1;" :: "r"(raddr), "f"(v) : "memory");
}

// ---------------- 0) permute w_hh -> [dir][j][g][k] ----------------
__global__ void transpose_whh(const float* __restrict__ whf,
                              const float* __restrict__ whb) {
    int idx = blockIdx.x * blockDim.x + threadIdx.x;
    if (idx >= 2 * H * G4) return;
    int dir = idx / (H * G4);
    int r = idx % (H * G4);
    int j = r / G4;
    int rr = r % G4;
    int g = rr / H;
    int k = rr % H;
    const float* W = dir ? whb : whf;
    d_wt[idx] = W[(size_t)(g * H + j) * H + k];
}

// ---------------- 1) embedding + layernorm ----------------
__global__ void embed_ln_kernel(const int* __restrict__ words,
                                const float* __restrict__ emb,
                                const float* __restrict__ gamma,
                                const float* __restrict__ beta) {
    int tok = blockIdx.x;
    int e = threadIdx.x;
    int lane = e & 31, w = e >> 5;
    int wd = words[tok];
    float v = emb[(size_t)wd * E + e];

    float s1 = v, s2 = v * v;
    #pragma unroll
    for (int o = 16; o > 0; o >>= 1) {
        s1 += __shfl_down_sync(0xffffffffu, s1, o);
        s2 += __shfl_down_sync(0xffffffffu, s2, o);
    }
    __shared__ float a1[8], a2[8];
    __shared__ float mu_s, rs_s;
    if (lane == 0) { a1[w] = s1; a2[w] = s2; }
    __syncthreads();
    if (e == 0) {
        float t1 = 0.f, t2 = 0.f;
        #pragma unroll
        for (int i = 0; i < 8; i++) { t1 += a1[i]; t2 += a2[i]; }
        float mu = t1 * (1.0f / E);
        float var = t2 * (1.0f / E) - mu * mu;
        mu_s = mu;
        rs_s = rsqrtf(var + LN_EPS);
    }
    __syncthreads();
    d_x[(size_t)tok * E + e] = (v - mu_s) * rs_s * gamma[e] + beta[e];
}

// ---------------- 2) input GEMM with f32x2 (k-pair) packing ----------------
// C[m,n] = sum_k A[m,k]*W[n,k] + bias[n]; 128x64x32 tiles, double-buffered.
__global__ void __launch_bounds__(256, 2)
gates_gemm(const float* __restrict__ w_f, const float* __restrict__ b_f,
           const float* __restrict__ w_b, const float* __restrict__ b_b) {
    extern __shared__ char gsm[];
    float2* As2 = (float2*)gsm;                              // [2][16][AS2STR]
    float2* Bs2 = (float2*)(gsm + 2 * 16 * AS2STR * 8);      // [2][16][BS2STR]

    int dir = blockIdx.z;
    const float* W = dir ? w_b : w_f;
    const float* bias = dir ? b_b : b_f;
    float* out = dir ? d_g1 : d_g0;

    int m0 = blockIdx.y * TBM;
    int n0 = blockIdx.x * TBN;

    int tid = threadIdx.x;
    int tx = tid & 15;      // n sub-tile (4 n)
    int ty = tid >> 4;      // m sub-tile (8 m)

    float4 areg[4], breg[2];

    auto ldAB = [&](int k0) {
        #pragma unroll
        for (int s2 = 0; s2 < 4; s2++) {
            int idx = tid + s2 * 256;
            int row = idx >> 3, c4 = idx & 7;
            areg[s2] = *(const float4*)(d_x + (size_t)(m0 + row) * E + k0 + c4 * 4);
        }
        #pragma unroll
        for (int s2 = 0; s2 < 2; s2++) {
            int idx = tid + s2 * 256;
            int n = idx >> 3, c4 = idx & 7;
            int gn = n0 + n;
            breg[s2] = (gn < G4) ? *(const float4*)(W + (size_t)gn * E + k0 + c4 * 4)
                                 : make_float4(0.f, 0.f, 0.f, 0.f);
        }
    };
    auto stAB = [&](int buf) {
        #pragma unroll
        for (int s2 = 0; s2 < 4; s2++) {
            int idx = tid + s2 * 256;
            int row = idx >> 3, c4 = idx & 7;
            float4 a = areg[s2];
            As2[(buf * 16 + 2 * c4) * AS2STR + row]     = make_float2(a.x, a.y);
            As2[(buf * 16 + 2 * c4 + 1) * AS2STR + row] = make_float2(a.z, a.w);
        }
        #pragma unroll
        for (int s2 = 0; s2 < 2; s2++) {
            int idx = tid + s2 * 256;
            int n = idx >> 3, c4 = idx & 7;
            float4 bvv = breg[s2];
            Bs2[(buf * 16 + 2 * c4) * BS2STR + n]     = make_float2(bvv.x, bvv.y);
            Bs2[(buf * 16 + 2 * c4 + 1) * BS2STR + n] = make_float2(bvv.z, bvv.w);
        }
    };

    ull acc[8][4];
    #pragma unroll
    for (int i = 0; i < 8; i++)
        #pragma unroll
        for (int j = 0; j < 4; j++) acc[i][j] = 0ull;

    ldAB(0);
    stAB(0);
    __syncthreads();

    #pragma unroll 1
    for (int kt = 0; kt < E / TBK; kt++) {
        if (kt < E / TBK - 1) ldAB((kt + 1) * TBK);
        int buf = kt & 1;
        #pragma unroll
        for (int kk2 = 0; kk2 < 16; kk2++) {
            ull a2[8], b2[4];
            const ulonglong2* ap =
                (const ulonglong2*)&As2[(buf * 16 + kk2) * AS2STR + ty * 8];
            const ulonglong2* bp =
                (const ulonglong2*)&Bs2[(buf * 16 + kk2) * BS2STR + tx * 4];
            #pragma unroll
            for (int u = 0; u < 4; u++) { ulonglong2 v = ap[u]; a2[2*u] = v.x; a2[2*u+1] = v.y; }
            #pragma unroll
            for (int u = 0; u < 2; u++) { ulonglong2 v = bp[u]; b2[2*u] = v.x; b2[2*u+1] = v.y; }
            #pragma unroll
            for (int i = 0; i < 8; i++)
                #pragma unroll
                for (int j = 0; j < 4; j++)
                    acc[i][j] = ffma2(a2[i], b2[j], acc[i][j]);
        }
        if (kt < E / TBK - 1) stAB((kt + 1) & 1);
        __syncthreads();
    }

    #pragma unroll
    for (int i = 0; i < 8; i++) {
        int m = m0 + ty * 8 + i;
        #pragma unroll
        for (int j = 0; j < 4; j++) {
            int n = n0 + tx * 4 + j;
            if (n < G4) {
                float2 v = uf2(acc[i][j]);
                out[(size_t)m * G4 + n] = v.x + v.y + bias[n];
            }
        }
    }
}

// ---------------- 3) LSTM: 4-CTA cluster, smem weights, f32x2 k-pair FMA ----------------
// 416 threads: tid -> jl=tid>>3 (unit, <50), b=(tid>>1)&3 (batch), ks=tid&1 (k half).
// Weights [jl][gate][k] in smem (strides tuned: every LDS.128 hits 8 distinct 16B slots).
// h double-buffered plain f32; (h[k],h[k+1]) pairs feed fma.rn.f32x2; partner via shfl.
__global__ void __cluster_dims__(4, 1, 1) lstm_cluster_kernel(const int* __restrict__ seq_len) {
    extern __shared__ __align__(16) float smemf[];
    float* wsm = smemf;                              // [UPC][4][200] padded WJSTR
    float* hbuf = smemf + UPC * WJSTR;               // [2][NBATCH][HPAD]

    int cid = blockIdx.x >> 2;
    uint32_t rank;
    asm("mov.u32 %0, %%cluster_ctarank;" : "=r"(rank));
    int dir = cid & 1;
    int grp = cid >> 1;
    int tid = threadIdx.x;

    const float* gates = dir ? d_g1 : d_g0;
    float* hs = dir ? d_hb : d_hf;

    // load this CTA's 50-unit weight slice (coalesced, padded rows)
    const float* gsrc = d_wt + (size_t)(dir * H + rank * UPC) * G4;
    for (int i = tid; i < UPC * G4; i += blockDim.x) {
        int jl = i / G4;
        int rem = i % G4;
        wsm[jl * WJSTR + rem] = gsrc[(size_t)jl * G4 + rem];
    }
    for (int i = tid; i < 2 * NBATCH * HPAD; i += blockDim.x) hbuf[i] = 0.f;

    int jl = tid >> 3;
    int b = (tid >> 1) & 3;
    int ks = tid & 1;
    int jlc = jl < UPC ? jl : UPC - 1;
    int jg = rank * UPC + jlc;
    int bg = grp * NBATCH + b;
    bool act = (jl < UPC) && (ks == 0);
    int L = seq_len[bg];
    float ckeep = 0.f, hkeep = 0.f;

    const float* wbase = wsm + jlc * WJSTR + ks * 100;

    cluster_sync_();   // weights + zeroed h visible cluster-wide

    for (int s = 0; s < T; s++) {
        int t = dir ? (T - 1 - s) : s;
        int cur = s & 1, nxt = cur ^ 1;

        float gi = 0.f, gf = 0.f, gg = 0.f, go = 0.f;
        if (ks == 0) {
            const float* gp = gates + ((size_t)bg * T + t) * G4;
            gi = gp[jg]; gf = gp[H + jg]; gg = gp[2 * H + jg]; go = gp[3 * H + jg];
        }

        const float* hrow = hbuf + (cur * NBATCH + b) * HPAD + ks * 100;
        ull aiA = 0, aiB = 0, afA = 0, afB = 0, agA = 0, agB = 0, aoA = 0, aoB = 0;
        #pragma unroll 5
        for (int i = 0; i < 25; i++) {
            ulonglong2 h2  = *(const ulonglong2*)(hrow + 4 * i);
            ulonglong2 wi2 = *(const ulonglong2*)(wbase + 0 * H + 4 * i);
            ulonglong2 wf2 = *(const ulonglong2*)(wbase + 1 * H + 4 * i);
            ulonglong2 wg2 = *(const ulonglong2*)(wbase + 2 * H + 4 * i);
            ulonglong2 wo2 = *(const ulonglong2*)(wbase + 3 * H + 4 * i);
            aiA = ffma2(wi2.x, h2.x, aiA); aiB = ffma2(wi2.y, h2.y, aiB);
            afA = ffma2(wf2.x, h2.x, afA); afB = ffma2(wf2.y, h2.y, afB);
            agA = ffma2(wg2.x, h2.x, agA); agB = ffma2(wg2.y, h2.y, agB);
            aoA = ffma2(wo2.x, h2.x, aoA); aoB = ffma2(wo2.y, h2.y, aoB);
        }
        float2 vA, vB;
        vA = uf2(aiA); vB = uf2(aiB); float ai = vA.x + vA.y + vB.x + vB.y;
        vA = uf2(afA); vB = uf2(afB); float af = vA.x + vA.y + vB.x + vB.y;
        vA = uf2(agA); vB = uf2(agB); float ag = vA.x + vA.y + vB.x + vB.y;
        vA = uf2(aoA); vB = uf2(aoB); float ao = vA.x + vA.y + vB.x + vB.y;
        ai += __shfl_xor_sync(0xffffffffu, ai, 1);
        af += __shfl_xor_sync(0xffffffffu, af, 1);
        ag += __shfl_xor_sync(0xffffffffu, ag, 1);
        ao += __shfl_xor_sync(0xffffffffu, ao, 1);

        if (act) {
            float ig = fsigm(ai + gi);
            float fg = fsigm(af + gf);
            float og = fsigm(ao + go);
            float cn = fg * ckeep + ig * ftanh(ag + gg);
            float hn = og * ftanh(cn);
            bool m = (t < L);
            float hv = m ? hn : hkeep;
            ckeep = m ? cn : ckeep;
            hkeep = hv;

            uint32_t laddr = (uint32_t)__cvta_generic_to_shared(
                &hbuf[(nxt * NBATCH + b) * HPAD + jg]);
            st_shared_cluster(laddr, 0, hv);
            st_shared_cluster(laddr, 1, hv);
            st_shared_cluster(laddr, 2, hv);
            st_shared_cluster(laddr, 3, hv);

            hs[((size_t)bg * T + t) * H + jg] = hv;
        }
        cluster_sync_();
    }
}

// ---------------- 4) FC + log-softmax ----------------
#define FTOK 8
__global__ void fc_ls_kernel(const float* __restrict__ fcw, const float* __restrict__ fcb) {
    __shared__ float shw[2 * H * C];
    __shared__ float shh[FTOK][2 * H];
    __shared__ float sfeat[FTOK][C];
    __shared__ float slse[FTOK];

    int tid = threadIdx.x;
    int tt = tid / C;
    int c = tid % C;
    int tok0 = blockIdx.x * FTOK;

    for (int idx = tid; idx < 2 * H * C; idx += FTOK * C) {
        int cc = idx / (2 * H);
        int k = idx % (2 * H);
        shw[k * C + cc] = fcw[idx];
    }
    for (int idx = tid; idx < FTOK * 2 * H; idx += FTOK * C) {
        int t = idx / (2 * H);
        int k = idx % (2 * H);
        size_t tok = tok0 + t;
        shh[t][k] = (k < H) ? d_hf[tok * H + k] : d_hb[tok * H + (k - H)];
    }
    __syncthreads();

    float acc = fcb[c];
    const float* hrow = shh[tt];
    #pragma unroll 8
    for (int k = 0; k < 2 * H; k++)
        acc += hrow[k] * shw[k * C + c];
    sfeat[tt][c] = acc;
    __syncthreads();

    if (c == 0) {
        float m = sfeat[tt][0];
        #pragma unroll
        for (int i = 1; i < C; i++) m = fmaxf(m, sfeat[tt][i]);
        float ssum = 0.f;
        #pragma unroll
        for (int i = 0; i < C; i++) ssum += __expf(sfeat[tt][i] - m);
        slse[tt] = m + __logf(ssum);
    }
    __syncthreads();
    d_logits[(size_t)(tok0 + tt) * C + c] = acc - slse[tt];
}

// ---------------- 5) CRF NLL (one warp per batch) ----------------
__global__ void crf_kernel(const int* __restrict__ target,
                           const int* __restrict__ seq_len,
                           const float* __restrict__ trans,
                           const float* __restrict__ sv,
                           const float* __restrict__ ev) {
    int b = blockIdx.x;
    int tid = threadIdx.x;
    __shared__ float tr[C * C];
    __shared__ float alpha[C];

    for (int i = tid; i < C * C; i += 32) tr[i] = trans[i];
    int L = seq_len[b];
    const int* tgt = target + (size_t)b * T;
    const float* lg = d_logits + (size_t)b * T * C;

    float acc = 0.f;
    for (int t = tid; t < L; t += 32) acc += lg[(size_t)t * C + tgt[t]];
    for (int t = 1 + tid; t < L; t += 32) acc += trans[tgt[t - 1] * C + tgt[t]];
    #pragma unroll
    for (int o = 16; o > 0; o >>= 1) acc += __shfl_down_sync(0xffffffffu, acc, o);

    __syncwarp();
    if (tid < C) alpha[tid] = sv[tid] + lg[tid];
    __syncwarp();

    float trcol[C];
    if (tid < C) {
        #pragma unroll
        for (int c1 = 0; c1 < C; c1++) trcol[c1] = tr[c1 * C + tid];
    }

    for (int t = 1; t < L; t++) {
        float na = 0.f;
        if (tid < C) {
            float v[C];
            #pragma unroll
            for (int c1 = 0; c1 < C; c1++) v[c1] = alpha[c1] + trcol[c1];
            float mx[C];
            #pragma unroll
            for (int c1 = 0; c1 < C; c1++) mx[c1] = v[c1];
            #pragma unroll
            for (int st = 1; st < C; st *= 2)
                #pragma unroll
                for (int i = 0; i + st < C; i += 2 * st) mx[i] = fmaxf(mx[i], mx[i + st]);
            float m = mx[0];
            #pragma unroll
            for (int c1 = 0; c1 < C; c1++) v[c1] = __expf(v[c1] - m);
            #pragma unroll
            for (int st = 1; st < C; st *= 2)
                #pragma unroll
                for (int i = 0; i + st < C; i += 2 * st) v[i] += v[i + st];
            na = m + __logf(v[0]) + lg[(size_t)t * C + tid];
        }
        __syncwarp();
        if (tid < C) alpha[tid] = na;
        __syncwarp();
    }

    if (tid == 0) {
        float m = -1e30f;
        #pragma unroll
        for (int c = 0; c < C; c++) m = fmaxf(m, alpha[c] + ev[c]);
        float ssum = 0.f;
        #pragma unroll
        for (int c = 0; c < C; c++) ssum += __expf(alpha[c] + ev[c] - m);
        float logZ = m + __logf(ssum);
        float gold = acc + sv[tgt[0]] + ev[tgt[L - 1]];
        d_loss[b] = logZ - gold;
    }
}

// ---------------- 6) mean ----------------
__global__ void mean_kernel(float* __restrict__ out) {
    int tid = threadIdx.x;
    __shared__ float red[B];
    red[tid] = d_loss[tid];
    __syncthreads();
    #pragma unroll
    for (int s = 32; s > 0; s >>= 1) {
        if (tid < s) red[tid] += red[tid + s];
        __syncthreads();
    }
    if (tid == 0) out[0] = red[0] * (1.0f / B);
}

// ---------------- launch ----------------
extern "C" void kernel_launch(void* const* d_in, const int* in_sizes, int n_in,
                              void* d_out, int out_size) {
    const int* words    = (const int*)d_in[0];
    const int* seq_len  = (const int*)d_in[1];
    const int* target   = (const int*)d_in[2];
    const float* embed  = (const float*)d_in[3];
    const float* gamma  = (const float*)d_in[4];
    const float* beta   = (const float*)d_in[5];
    const float* wihf   = (const float*)d_in[6];
    const float* whhf   = (const float*)d_in[7];
    const float* bf     = (const float*)d_in[8];
    const float* wihb   = (const float*)d_in[9];
    const float* whhb   = (const float*)d_in[10];
    const float* bb     = (const float*)d_in[11];
    const float* fcw    = (const float*)d_in[12];
    const float* fcb    = (const float*)d_in[13];
    const float* trans  = (const float*)d_in[14];
    const float* sv     = (const float*)d_in[15];
    const float* ev     = (const float*)d_in[16];
    float* out = (float*)d_out;

    cudaFuncSetAttribute(lstm_cluster_kernel,
                         cudaFuncAttributeMaxDynamicSharedMemorySize, LSTM_SMEM);
    cudaFuncSetAttribute(gates_gemm,
                         cudaFuncAttributeMaxDynamicSharedMemorySize, GEMM_SMEM);

    transpose_whh<<<(2 * H * G4 + 255) / 256, 256>>>(whhf, whhb);

    embed_ln_kernel<<<B * T, 256>>>(words, embed, gamma, beta);

    dim3 ggrid((G4 + TBN - 1) / TBN, (B * T) / TBM, 2);
    gates_gemm<<<ggrid, 256, GEMM_SMEM>>>(wihf, bf, wihb, bb);

    lstm_cluster_kernel<<<128, 416, LSTM_SMEM>>>(seq_len);

    fc_ls_kernel<<<(B * T) / FTOK, FTOK * C>>>(fcw, fcb);

    crf_kernel<<<B, 32>>>(target, seq_len, trans, sv, ev);

    mean_kernel<<<1, B>>>(out);
}

// round 10
// speedup vs baseline: 4.4865x; 1.0190x over previous
#include <cuda_runtime.h>
#include <cuda_bf16.h>
#include <math.h>
#include <stdint.h>

#define B 64
#define T 512
#define E 256
#define H 200
#define G4 800   // 4*H
#define C 20
#define LN_EPS 1e-5f

typedef unsigned long long ull;

// LSTM cluster config
#define UPC 50          // hidden units per CTA (4 CTAs/cluster -> 200)
#define NBATCH 4        // batches per cluster
#define SEG 25          // k per segment (8 segments cover H=200)
#define SEGP 36         // padded seg stride in h rows (distinct banks @16B granularity)
#define HROW (8 * SEGP) // 288 floats per (buf, batch) h row

// GEMM config
#define TBM 128
#define TBN 64
#define TBK 32
#define AS2STR 132
#define BS2STR 68
#define GEMM_SMEM (2 * (TBK/2) * AS2STR * 8 + 2 * (TBK/2) * BS2STR * 8)  // 51200

// ---------------- scratch (device globals; no allocation) ----------------
__device__ float d_x[(size_t)B * T * E];
__device__ float d_g0[(size_t)B * T * G4];
__device__ float d_g1[(size_t)B * T * G4];
__device__ float d_hf[(size_t)B * T * H];
__device__ float d_hb[(size_t)B * T * H];
__device__ float d_logits[(size_t)B * T * C];
__device__ float d_loss[B];
__device__ float d_wt[2 * H * G4];   // [dir][unit j][gate g][k]

__device__ __forceinline__ float fsigm(float x) {
    return __fdividef(1.f, 1.f + __expf(-x));
}
__device__ __forceinline__ float ftanh(float x) {
    return __fdividef(2.f, 1.f + __expf(-2.f * x)) - 1.f;
}
__device__ __forceinline__ ull ffma2(ull a, ull b, ull c) {
    ull d;
    asm("fma.rn.f32x2 %0, %1, %2, %3;" : "=l"(d) : "l"(a), "l"(b), "l"(c));
    return d;
}
__device__ __forceinline__ float2 uf2(ull u) {
    float2 f;
    f.x = __uint_as_float((unsigned)(u & 0xffffffffu));
    f.y = __uint_as_float((unsigned)(u >> 32));
    return f;
}
__device__ __forceinline__ ull packf2(float lo, float hi) {
    return (ull)__float_as_uint(lo) | ((ull)__float_as_uint(hi) << 32);
}
__device__ __forceinline__ void cluster_sync_() {
    asm volatile("barrier.cluster.arrive.aligned;" ::: "memory");
    asm volatile("barrier.cluster.wait.aligned;" ::: "memory");
}
__device__ __forceinline__ void st_shared_cluster(uint32_t laddr, int rank, float v) {
    uint32_t raddr;
    asm volatile("mapa.shared::cluster.u32 %0, %1, %2;" : "=r"(raddr) : "r"(laddr), "r"(rank));
    asm volatile("st.shared::cluster.f32 [%0], %1;" :: "r"(raddr), "f"(v) : "memory");
}

// ---------------- 0) permute w_hh -> [dir][j][g][k] ----------------
__global__ void transpose_whh(const float* __restrict__ whf,
                              const float* __restrict__ whb) {
    int idx = blockIdx.x * blockDim.x + threadIdx.x;
    if (idx >= 2 * H * G4) return;
    int dir = idx / (H * G4);
    int r = idx % (H * G4);
    int j = r / G4;
    int rr = r % G4;
    int g = rr / H;
    int k = rr % H;
    const float* W = dir ? whb : whf;
    d_wt[idx] = W[(size_t)(g * H + j) * H + k];
}

// ---------------- 1) embedding + layernorm ----------------
__global__ void embed_ln_kernel(const int* __restrict__ words,
                                const float* __restrict__ emb,
                                const float* __restrict__ gamma,
                                const float* __restrict__ beta) {
    int tok = blockIdx.x;
    int e = threadIdx.x;
    int lane = e & 31, w = e >> 5;
    int wd = words[tok];
    float v = emb[(size_t)wd * E + e];

    float s1 = v, s2 = v * v;
    #pragma unroll
    for (int o = 16; o > 0; o >>= 1) {
        s1 += __shfl_down_sync(0xffffffffu, s1, o);
        s2 += __shfl_down_sync(0xffffffffu, s2, o);
    }
    __shared__ float a1[8], a2[8];
    __shared__ float mu_s, rs_s;
    if (lane == 0) { a1[w] = s1; a2[w] = s2; }
    __syncthreads();
    if (e == 0) {
        float t1 = 0.f, t2 = 0.f;
        #pragma unroll
        for (int i = 0; i < 8; i++) { t1 += a1[i]; t2 += a2[i]; }
        float mu = t1 * (1.0f / E);
        float var = t2 * (1.0f / E) - mu * mu;
        mu_s = mu;
        rs_s = rsqrtf(var + LN_EPS);
    }
    __syncthreads();
    d_x[(size_t)tok * E + e] = (v - mu_s) * rs_s * gamma[e] + beta[e];
}

// ---------------- 2) input GEMM with f32x2 (k-pair) packing ----------------
__global__ void __launch_bounds__(256, 2)
gates_gemm(const float* __restrict__ w_f, const float* __restrict__ b_f,
           const float* __restrict__ w_b, const float* __restrict__ b_b) {
    extern __shared__ char gsm[];
    float2* As2 = (float2*)gsm;                              // [2][16][AS2STR]
    float2* Bs2 = (float2*)(gsm + 2 * 16 * AS2STR * 8);      // [2][16][BS2STR]

    int dir = blockIdx.z;
    const float* W = dir ? w_b : w_f;
    const float* bias = dir ? b_b : b_f;
    float* out = dir ? d_g1 : d_g0;

    int m0 = blockIdx.y * TBM;
    int n0 = blockIdx.x * TBN;

    int tid = threadIdx.x;
    int tx = tid & 15;
    int ty = tid >> 4;

    float4 areg[4], breg[2];

    auto ldAB = [&](int k0) {
        #pragma unroll
        for (int s2 = 0; s2 < 4; s2++) {
            int idx = tid + s2 * 256;
            int row = idx >> 3, c4 = idx & 7;
            areg[s2] = *(const float4*)(d_x + (size_t)(m0 + row) * E + k0 + c4 * 4);
        }
        #pragma unroll
        for (int s2 = 0; s2 < 2; s2++) {
            int idx = tid + s2 * 256;
            int n = idx >> 3, c4 = idx & 7;
            int gn = n0 + n;
            breg[s2] = (gn < G4) ? *(const float4*)(W + (size_t)gn * E + k0 + c4 * 4)
                                 : make_float4(0.f, 0.f, 0.f, 0.f);
        }
    };
    auto stAB = [&](int buf) {
        #pragma unroll
        for (int s2 = 0; s2 < 4; s2++) {
            int idx = tid + s2 * 256;
            int row = idx >> 3, c4 = idx & 7;
            float4 a = areg[s2];
            As2[(buf * 16 + 2 * c4) * AS2STR + row]     = make_float2(a.x, a.y);
            As2[(buf * 16 + 2 * c4 + 1) * AS2STR + row] = make_float2(a.z, a.w);
        }
        #pragma unroll
        for (int s2 = 0; s2 < 2; s2++) {
            int idx = tid + s2 * 256;
            int n = idx >> 3, c4 = idx & 7;
            float4 bvv = breg[s2];
            Bs2[(buf * 16 + 2 * c4) * BS2STR + n]     = make_float2(bvv.x, bvv.y);
            Bs2[(buf * 16 + 2 * c4 + 1) * BS2STR + n] = make_float2(bvv.z, bvv.w);
        }
    };

    ull acc[8][4];
    #pragma unroll
    for (int i = 0; i < 8; i++)
        #pragma unroll
        for (int j = 0; j < 4; j++) acc[i][j] = 0ull;

    ldAB(0);
    stAB(0);
    __syncthreads();

    #pragma unroll 1
    for (int kt = 0; kt < E / TBK; kt++) {
        if (kt < E / TBK - 1) ldAB((kt + 1) * TBK);
        int buf = kt & 1;
        #pragma unroll
        for (int kk2 = 0; kk2 < 16; kk2++) {
            ull a2[8], b2[4];
            const ulonglong2* ap =
                (const ulonglong2*)&As2[(buf * 16 + kk2) * AS2STR + ty * 8];
            const ulonglong2* bp =
                (const ulonglong2*)&Bs2[(buf * 16 + kk2) * BS2STR + tx * 4];
            #pragma unroll
            for (int u = 0; u < 4; u++) { ulonglong2 v = ap[u]; a2[2*u] = v.x; a2[2*u+1] = v.y; }
            #pragma unroll
            for (int u = 0; u < 2; u++) { ulonglong2 v = bp[u]; b2[2*u] = v.x; b2[2*u+1] = v.y; }
            #pragma unroll
            for (int i = 0; i < 8; i++)
                #pragma unroll
                for (int j = 0; j < 4; j++)
                    acc[i][j] = ffma2(a2[i], b2[j], acc[i][j]);
        }
        if (kt < E / TBK - 1) stAB((kt + 1) & 1);
        __syncthreads();
    }

    #pragma unroll
    for (int i = 0; i < 8; i++) {
        int m = m0 + ty * 8 + i;
        #pragma unroll
        for (int j = 0; j < 4; j++) {
            int n = n0 + tx * 4 + j;
            if (n < G4) {
                float2 v = uf2(acc[i][j]);
                out[(size_t)m * G4 + n] = v.x + v.y + bias[n];
            }
        }
    }
}

// ---------------- 3) LSTM: register-resident weights, 4-CTA cluster ----------------
// 400 threads: tid -> jl=tid>>3 (unit 0..49), ks=tid&7 (k-segment of 25).
// Each thread holds its unit's 4-gate x 26(padded) weight slice in registers
// (52 f32x2). Batch-outer loop reads only h from smem (broadcast, bank-tuned
// stride SEGP=36), 12 shfl-xor reduce per batch across the 8 k-segments.
// Lane ks==b owns batch b's cell update + DSMEM h broadcast.
__global__ void __cluster_dims__(4, 1, 1) __launch_bounds__(400, 1)
lstm_cluster_kernel(const int* __restrict__ seq_len) {
    __shared__ __align__(16) float hbuf[2][NBATCH][HROW];

    int cid = blockIdx.x >> 2;
    uint32_t rank;
    asm("mov.u32 %0, %%cluster_ctarank;" : "=r"(rank));
    int dir = cid & 1;
    int grp = cid >> 1;
    int tid = threadIdx.x;
    int jl = tid >> 3;
    int ks = tid & 7;
    int jg = rank * UPC + jl;

    const float* gates = dir ? d_g1 : d_g0;
    float* hs = dir ? d_hb : d_hf;

    // load this thread's weight slice into registers: wreg[g][p] = (W[k0+2p], W[k0+2p+1])
    ull wreg[4][13];
    {
        const float* wb = d_wt + (size_t)(dir * H + jg) * G4;   // [g][k]
        int k0 = ks * SEG;
        #pragma unroll
        for (int g = 0; g < 4; g++) {
            #pragma unroll
            for (int p = 0; p < 13; p++) {
                float lo = wb[g * H + k0 + 2 * p];
                float hi = (2 * p + 1 < SEG) ? wb[g * H + k0 + 2 * p + 1] : 0.f;
                wreg[g][p] = packf2(lo, hi);
            }
        }
    }
    // zero h double buffer (pad slots stay 0 forever)
    for (int i = tid; i < 2 * NBATCH * HROW; i += 400) ((float*)hbuf)[i] = 0.f;

    bool owner = (ks < NBATCH);
    int bg = grp * NBATCH + (ks & 3);
    int L = seq_len[bg];
    float ckeep = 0.f, hkeep = 0.f;
    int hseg = jg / SEG, hoff = jg % SEG;

    cluster_sync_();   // zeroed h visible cluster-wide

    for (int s = 0; s < T; s++) {
        int t = dir ? (T - 1 - s) : s;
        int cur = s & 1, nxt = cur ^ 1;

        float gi = 0.f, gf = 0.f, gg = 0.f, go = 0.f;
        if (owner) {
            const float* gp = gates + ((size_t)bg * T + t) * G4;
            gi = gp[jg]; gf = gp[H + jg]; gg = gp[2 * H + jg]; go = gp[3 * H + jg];
        }

        float ai = 0.f, af = 0.f, ag = 0.f, ao = 0.f;
        #pragma unroll
        for (int b = 0; b < NBATCH; b++) {
            const float* hr = &hbuf[cur][b][ks * SEGP];
            ull a0 = 0, a1 = 0, a2 = 0, a3 = 0;
            #pragma unroll
            for (int q = 0; q < 6; q++) {
                ulonglong2 h2 = *(const ulonglong2*)(hr + 4 * q);
                a0 = ffma2(wreg[0][2 * q], h2.x, a0);
                a1 = ffma2(wreg[1][2 * q], h2.x, a1);
                a2 = ffma2(wreg[2][2 * q], h2.x, a2);
                a3 = ffma2(wreg[3][2 * q], h2.x, a3);
                a0 = ffma2(wreg[0][2 * q + 1], h2.y, a0);
                a1 = ffma2(wreg[1][2 * q + 1], h2.y, a1);
                a2 = ffma2(wreg[2][2 * q + 1], h2.y, a2);
                a3 = ffma2(wreg[3][2 * q + 1], h2.y, a3);
            }
            {
                ull hl = *(const ull*)(hr + 24);   // pair 12 (k 24, pad)
                a0 = ffma2(wreg[0][12], hl, a0);
                a1 = ffma2(wreg[1][12], hl, a1);
                a2 = ffma2(wreg[2][12], hl, a2);
                a3 = ffma2(wreg[3][12], hl, a3);
            }
            float2 v;
            v = uf2(a0); float r0 = v.x + v.y;
            v = uf2(a1); float r1 = v.x + v.y;
            v = uf2(a2); float r2 = v.x + v.y;
            v = uf2(a3); float r3 = v.x + v.y;
            #pragma unroll
            for (int o = 1; o < 8; o <<= 1) {
                r0 += __shfl_xor_sync(0xffffffffu, r0, o);
                r1 += __shfl_xor_sync(0xffffffffu, r1, o);
                r2 += __shfl_xor_sync(0xffffffffu, r2, o);
                r3 += __shfl_xor_sync(0xffffffffu, r3, o);
            }
            if (ks == b) { ai = r0; af = r1; ag = r2; ao = r3; }
        }

        if (owner) {
            float igt = fsigm(ai + gi);
            float fgt = fsigm(af + gf);
            float ogt = fsigm(ao + go);
            float cn = fgt * ckeep + igt * ftanh(ag + gg);
            float hn = ogt * ftanh(cn);
            bool m = (t < L);
            float hv = m ? hn : hkeep;
            ckeep = m ? cn : ckeep;
            hkeep = hv;

            uint32_t laddr = (uint32_t)__cvta_generic_to_shared(
                &hbuf[nxt][ks][hseg * SEGP + hoff]);
            st_shared_cluster(laddr, 0, hv);
            st_shared_cluster(laddr, 1, hv);
            st_shared_cluster(laddr, 2, hv);
            st_shared_cluster(laddr, 3, hv);

            hs[((size_t)bg * T + t) * H + jg] = hv;
        }
        cluster_sync_();
    }
}

// ---------------- 4) FC + log-softmax ----------------
#define FTOK 8
__global__ void fc_ls_kernel(const float* __restrict__ fcw, const float* __restrict__ fcb) {
    __shared__ float shw[2 * H * C];
    __shared__ float shh[FTOK][2 * H];
    __shared__ float sfeat[FTOK][C];
    __shared__ float slse[FTOK];

    int tid = threadIdx.x;
    int tt = tid / C;
    int c = tid % C;
    int tok0 = blockIdx.x * FTOK;

    for (int idx = tid; idx < 2 * H * C; idx += FTOK * C) {
        int cc = idx / (2 * H);
        int k = idx % (2 * H);
        shw[k * C + cc] = fcw[idx];
    }
    for (int idx = tid; idx < FTOK * 2 * H; idx += FTOK * C) {
        int t = idx / (2 * H);
        int k = idx % (2 * H);
        size_t tok = tok0 + t;
        shh[t][k] = (k < H) ? d_hf[tok * H + k] : d_hb[tok * H + (k - H)];
    }
    __syncthreads();

    float acc = fcb[c];
    const float* hrow = shh[tt];
    #pragma unroll 8
    for (int k = 0; k < 2 * H; k++)
        acc += hrow[k] * shw[k * C + c];
    sfeat[tt][c] = acc;
    __syncthreads();

    if (c == 0) {
        float m = sfeat[tt][0];
        #pragma unroll
        for (int i = 1; i < C; i++) m = fmaxf(m, sfeat[tt][i]);
        float ssum = 0.f;
        #pragma unroll
        for (int i = 0; i < C; i++) ssum += __expf(sfeat[tt][i] - m);
        slse[tt] = m + __logf(ssum);
    }
    __syncthreads();
    d_logits[(size_t)(tok0 + tt) * C + c] = acc - slse[tt];
}

// ---------------- 5) CRF NLL (one warp per batch) ----------------
__global__ void crf_kernel(const int* __restrict__ target,
                           const int* __restrict__ seq_len,
                           const float* __restrict__ trans,
                           const float* __restrict__ sv,
                           const float* __restrict__ ev) {
    int b = blockIdx.x;
    int tid = threadIdx.x;
    __shared__ float tr[C * C];
    __shared__ float alpha[C];

    for (int i = tid; i < C * C; i += 32) tr[i] = trans[i];
    int L = seq_len[b];
    const int* tgt = target + (size_t)b * T;
    const float* lg = d_logits + (size_t)b * T * C;

    float acc = 0.f;
    for (int t = tid; t < L; t += 32) acc += lg[(size_t)t * C + tgt[t]];
    for (int t = 1 + tid; t < L; t += 32) acc += trans[tgt[t - 1] * C + tgt[t]];
    #pragma unroll
    for (int o = 16; o > 0; o >>= 1) acc += __shfl_down_sync(0xffffffffu, acc, o);

    __syncwarp();
    if (tid < C) alpha[tid] = sv[tid] + lg[tid];
    __syncwarp();

    float trcol[C];
    if (tid < C) {
        #pragma unroll
        for (int c1 = 0; c1 < C; c1++) trcol[c1] = tr[c1 * C + tid];
    }

    for (int t = 1; t < L; t++) {
        float na = 0.f;
        if (tid < C) {
            float v[C];
            #pragma unroll
            for (int c1 = 0; c1 < C; c1++) v[c1] = alpha[c1] + trcol[c1];
            float mx[C];
            #pragma unroll
            for (int c1 = 0; c1 < C; c1++) mx[c1] = v[c1];
            #pragma unroll
            for (int st = 1; st < C; st *= 2)
                #pragma unroll
                for (int i = 0; i + st < C; i += 2 * st) mx[i] = fmaxf(mx[i], mx[i + st]);
            float m = mx[0];
            #pragma unroll
            for (int c1 = 0; c1 < C; c1++) v[c1] = __expf(v[c1] - m);
            #pragma unroll
            for (int st = 1; st < C; st *= 2)
                #pragma unroll
                for (int i = 0; i + st < C; i += 2 * st) v[i] += v[i + st];
            na = m + __logf(v[0]) + lg[(size_t)t * C + tid];
        }
        __syncwarp();
        if (tid < C) alpha[tid] = na;
        __syncwarp();
    }

    if (tid == 0) {
        float m = -1e30f;
        #pragma unroll
        for (int c = 0; c < C; c++) m = fmaxf(m, alpha[c] + ev[c]);
        float ssum = 0.f;
        #pragma unroll
        for (int c = 0; c < C; c++) ssum += __expf(alpha[c] + ev[c] - m);
        float logZ = m + __logf(ssum);
        float gold = acc + sv[tgt[0]] + ev[tgt[L - 1]];
        d_loss[b] = logZ - gold;
    }
}

// ---------------- 6) mean ----------------
__global__ void mean_kernel(float* __restrict__ out) {
    int tid = threadIdx.x;
    __shared__ float red[B];
    red[tid] = d_loss[tid];
    __syncthreads();
    #pragma unroll
    for (int s = 32; s > 0; s >>= 1) {
        if (tid < s) red[tid] += red[tid + s];
        __syncthreads();
    }
    if (tid == 0) out[0] = red[0] * (1.0f / B);
}

// ---------------- launch ----------------
extern "C" void kernel_launch(void* const* d_in, const int* in_sizes, int n_in,
                              void* d_out, int out_size) {
    const int* words    = (const int*)d_in[0];
    const int* seq_len  = (const int*)d_in[1];
    const int* target   = (const int*)d_in[2];
    const float* embed  = (const float*)d_in[3];
    const float* gamma  = (const float*)d_in[4];
    const float* beta   = (const float*)d_in[5];
    const float* wihf   = (const float*)d_in[6];
    const float* whhf   = (const float*)d_in[7];
    const float* bf     = (const float*)d_in[8];
    const float* wihb   = (const float*)d_in[9];
    const float* whhb   = (const float*)d_in[10];
    const float* bb     = (const float*)d_in[11];
    const float* fcw    = (const float*)d_in[12];
    const float* fcb    = (const float*)d_in[13];
    const float* trans  = (const float*)d_in[14];
    const float* sv     = (const float*)d_in[15];
    const float* ev     = (const float*)d_in[16];
    float* out = (float*)d_out;

    cudaFuncSetAttribute(gates_gemm,
                         cudaFuncAttributeMaxDynamicSharedMemorySize, GEMM_SMEM);

    transpose_whh<<<(2 * H * G4 + 255) / 256, 256>>>(whhf, whhb);

    embed_ln_kernel<<<B * T, 256>>>(words, embed, gamma, beta);

    dim3 ggrid((G4 + TBN - 1) / TBN, (B * T) / TBM, 2);
    gates_gemm<<<ggrid, 256, GEMM_SMEM>>>(wihf, bf, wihb, bb);

    lstm_cluster_kernel<<<128, 400>>>(seq_len);

    fc_ls_kernel<<<(B * T) / FTOK, FTOK * C>>>(fcw, fcb);

    crf_kernel<<<B, 32>>>(target, seq_len, trans, sv, ev);

    mean_kernel<<<1, B>>>(out);
}

// round 11
// speedup vs baseline: 5.0658x; 1.1291x over previous
#include <cuda_runtime.h>
#include <cuda_bf16.h>
#include <math.h>
#include <stdint.h>

#define B 64
#define T 512
#define E 256
#define H 200
#define G4 800   // 4*H
#define C 20
#define LN_EPS 1e-5f

typedef unsigned long long ull;

// LSTM cluster config
#define UPC 50          // hidden units per CTA (4 CTAs/cluster -> 200)
#define NBATCH 4        // batches per cluster
#define SEG 25          // k per segment (8 segments cover H=200)
#define SEGP 36         // padded seg stride in h rows
#define HROW (8 * SEGP) // 288 floats per (buf, batch) h row

// GEMM config
#define TBM 128
#define TBN 64
#define TBK 32
#define AS2STR 132
#define BS2STR 68
#define GEMM_SMEM (2 * (TBK/2) * AS2STR * 8 + 2 * (TBK/2) * BS2STR * 8)  // 51200

// ---------------- scratch (device globals; no allocation) ----------------
__device__ float d_x[(size_t)B * T * E];
__device__ float d_g0[(size_t)B * T * G4];
__device__ float d_g1[(size_t)B * T * G4];
__device__ float d_hf[(size_t)B * T * H];
__device__ float d_hb[(size_t)B * T * H];
__device__ float d_logits[(size_t)B * T * C];
__device__ float d_loss[B];
__device__ float d_wt[2 * H * G4];   // [dir][unit j][gate g][k]

__device__ __forceinline__ float tanh_ap(float x) {
    float y;
    asm("tanh.approx.f32 %0, %1;" : "=f"(y) : "f"(x));
    return y;
}
__device__ __forceinline__ float fsigm(float x) {
    return fmaf(0.5f, tanh_ap(0.5f * x), 0.5f);
}
__device__ __forceinline__ float ftanh(float x) {
    return tanh_ap(x);
}
__device__ __forceinline__ ull ffma2(ull a, ull b, ull c) {
    ull d;
    asm("fma.rn.f32x2 %0, %1, %2, %3;" : "=l"(d) : "l"(a), "l"(b), "l"(c));
    return d;
}
__device__ __forceinline__ float2 uf2(ull u) {
    float2 f;
    f.x = __uint_as_float((unsigned)(u & 0xffffffffu));
    f.y = __uint_as_float((unsigned)(u >> 32));
    return f;
}
__device__ __forceinline__ ull packf2(float lo, float hi) {
    return (ull)__float_as_uint(lo) | ((ull)__float_as_uint(hi) << 32);
}
__device__ __forceinline__ void cluster_sync_() {
    asm volatile("barrier.cluster.arrive.aligned;" ::: "memory");
    asm volatile("barrier.cluster.wait.aligned;" ::: "memory");
}
__device__ __forceinline__ void cluster_arrive_() {
    asm volatile("barrier.cluster.arrive.aligned;" ::: "memory");
}
__device__ __forceinline__ void cluster_wait_() {
    asm volatile("barrier.cluster.wait.aligned;" ::: "memory");
}
__device__ __forceinline__ void st_shared_cluster(uint32_t laddr, int rank, float v) {
    uint32_t raddr;
    asm volatile("mapa.shared::cluster.u32 %0, %1, %2;" : "=r"(raddr) : "r"(laddr), "r"(rank));
    asm volatile("st.shared::cluster.f32 [%0], %1;" :: "r"(raddr), "f"(v) : "memory");
}

// ---------------- 0) permute w_hh -> [dir][j][g][k] ----------------
__global__ void transpose_whh(const float* __restrict__ whf,
                              const float* __restrict__ whb) {
    int idx = blockIdx.x * blockDim.x + threadIdx.x;
    if (idx >= 2 * H * G4) return;
    int dir = idx / (H * G4);
    int r = idx % (H * G4);
    int j = r / G4;
    int rr = r % G4;
    int g = rr / H;
    int k = rr % H;
    const float* W = dir ? whb : whf;
    d_wt[idx] = W[(size_t)(g * H + j) * H + k];
}

// ---------------- 1) embedding + layernorm ----------------
__global__ void embed_ln_kernel(const int* __restrict__ words,
                                const float* __restrict__ emb,
                                const float* __restrict__ gamma,
                                const float* __restrict__ beta) {
    int tok = blockIdx.x;
    int e = threadIdx.x;
    int lane = e & 31, w = e >> 5;
    int wd = words[tok];
    float v = emb[(size_t)wd * E + e];

    float s1 = v, s2 = v * v;
    #pragma unroll
    for (int o = 16; o > 0; o >>= 1) {
        s1 += __shfl_down_sync(0xffffffffu, s1, o);
        s2 += __shfl_down_sync(0xffffffffu, s2, o);
    }
    __shared__ float a1[8], a2[8];
    __shared__ float mu_s, rs_s;
    if (lane == 0) { a1[w] = s1; a2[w] = s2; }
    __syncthreads();
    if (e == 0) {
        float t1 = 0.f, t2 = 0.f;
        #pragma unroll
        for (int i = 0; i < 8; i++) { t1 += a1[i]; t2 += a2[i]; }
        float mu = t1 * (1.0f / E);
        float var = t2 * (1.0f / E) - mu * mu;
        mu_s = mu;
        rs_s = rsqrtf(var + LN_EPS);
    }
    __syncthreads();
    d_x[(size_t)tok * E + e] = (v - mu_s) * rs_s * gamma[e] + beta[e];
}

// ---------------- 2) input GEMM with f32x2 (k-pair) packing ----------------
__global__ void __launch_bounds__(256, 2)
gates_gemm(const float* __restrict__ w_f, const float* __restrict__ b_f,
           const float* __restrict__ w_b, const float* __restrict__ b_b) {
    extern __shared__ char gsm[];
    float2* As2 = (float2*)gsm;                              // [2][16][AS2STR]
    float2* Bs2 = (float2*)(gsm + 2 * 16 * AS2STR * 8);      // [2][16][BS2STR]

    int dir = blockIdx.z;
    const float* W = dir ? w_b : w_f;
    const float* bias = dir ? b_b : b_f;
    float* out = dir ? d_g1 : d_g0;

    int m0 = blockIdx.y * TBM;
    int n0 = blockIdx.x * TBN;

    int tid = threadIdx.x;
    int tx = tid & 15;
    int ty = tid >> 4;

    float4 areg[4], breg[2];

    auto ldAB = [&](int k0) {
        #pragma unroll
        for (int s2 = 0; s2 < 4; s2++) {
            int idx = tid + s2 * 256;
            int row = idx >> 3, c4 = idx & 7;
            areg[s2] = *(const float4*)(d_x + (size_t)(m0 + row) * E + k0 + c4 * 4);
        }
        #pragma unroll
        for (int s2 = 0; s2 < 2; s2++) {
            int idx = tid + s2 * 256;
            int n = idx >> 3, c4 = idx & 7;
            int gn = n0 + n;
            breg[s2] = (gn < G4) ? *(const float4*)(W + (size_t)gn * E + k0 + c4 * 4)
                                 : make_float4(0.f, 0.f, 0.f, 0.f);
        }
    };
    auto stAB = [&](int buf) {
        #pragma unroll
        for (int s2 = 0; s2 < 4; s2++) {
            int idx = tid + s2 * 256;
            int row = idx >> 3, c4 = idx & 7;
            float4 a = areg[s2];
            As2[(buf * 16 + 2 * c4) * AS2STR + row]     = make_float2(a.x, a.y);
            As2[(buf * 16 + 2 * c4 + 1) * AS2STR + row] = make_float2(a.z, a.w);
        }
        #pragma unroll
        for (int s2 = 0; s2 < 2; s2++) {
            int idx = tid + s2 * 256;
            int n = idx >> 3, c4 = idx & 7;
            float4 bvv = breg[s2];
            Bs2[(buf * 16 + 2 * c4) * BS2STR + n]     = make_float2(bvv.x, bvv.y);
            Bs2[(buf * 16 + 2 * c4 + 1) * BS2STR + n] = make_float2(bvv.z, bvv.w);
        }
    };

    ull acc[8][4];
    #pragma unroll
    for (int i = 0; i < 8; i++)
        #pragma unroll
        for (int j = 0; j < 4; j++) acc[i][j] = 0ull;

    ldAB(0);
    stAB(0);
    __syncthreads();

    #pragma unroll 1
    for (int kt = 0; kt < E / TBK; kt++) {
        if (kt < E / TBK - 1) ldAB((kt + 1) * TBK);
        int buf = kt & 1;
        #pragma unroll
        for (int kk2 = 0; kk2 < 16; kk2++) {
            ull a2[8], b2[4];
            const ulonglong2* ap =
                (const ulonglong2*)&As2[(buf * 16 + kk2) * AS2STR + ty * 8];
            const ulonglong2* bp =
                (const ulonglong2*)&Bs2[(buf * 16 + kk2) * BS2STR + tx * 4];
            #pragma unroll
            for (int u = 0; u < 4; u++) { ulonglong2 v = ap[u]; a2[2*u] = v.x; a2[2*u+1] = v.y; }
            #pragma unroll
            for (int u = 0; u < 2; u++) { ulonglong2 v = bp[u]; b2[2*u] = v.x; b2[2*u+1] = v.y; }
            #pragma unroll
            for (int i = 0; i < 8; i++)
                #pragma unroll
                for (int j = 0; j < 4; j++)
                    acc[i][j] = ffma2(a2[i], b2[j], acc[i][j]);
        }
        if (kt < E / TBK - 1) stAB((kt + 1) & 1);
        __syncthreads();
    }

    // vectorized epilogue: one STG.128 per (i); bias hoisted (n aligned to 4)
    int n = n0 + tx * 4;
    if (n < G4) {
        float4 bias4 = *(const float4*)(bias + n);
        #pragma unroll
        for (int i = 0; i < 8; i++) {
            int m = m0 + ty * 8 + i;
            float2 v0 = uf2(acc[i][0]);
            float2 v1 = uf2(acc[i][1]);
            float2 v2 = uf2(acc[i][2]);
            float2 v3 = uf2(acc[i][3]);
            float4 o4;
            o4.x = v0.x + v0.y + bias4.x;
            o4.y = v1.x + v1.y + bias4.y;
            o4.z = v2.x + v2.y + bias4.z;
            o4.w = v3.x + v3.y + bias4.w;
            *(float4*)(out + (size_t)m * G4 + n) = o4;
        }
    }
}

// ---------------- 3) LSTM: register weights, 4-CTA cluster, split barrier ----------------
// 400 threads: jl=tid>>3 (unit 0..49), ks=tid&7 (k-segment of 25).
// Weights in registers (52 f32x2/thread). Per step: FMA over 4 batches from
// smem h, 3-level shfl reduce, tanh.approx activations, DSMEM h broadcast,
// then arrive -> prefetch next gates -> wait (overlaps LDG + barrier skew).
__global__ void __cluster_dims__(4, 1, 1) __launch_bounds__(400, 1)
lstm_cluster_kernel(const int* __restrict__ seq_len) {
    __shared__ __align__(16) float hbuf[2][NBATCH][HROW];

    int cid = blockIdx.x >> 2;
    uint32_t rank;
    asm("mov.u32 %0, %%cluster_ctarank;" : "=r"(rank));
    int dir = cid & 1;
    int grp = cid >> 1;
    int tid = threadIdx.x;
    int jl = tid >> 3;
    int ks = tid & 7;
    int jg = rank * UPC + jl;

    const float* gates = dir ? d_g1 : d_g0;
    float* hs = dir ? d_hb : d_hf;

    // weights into registers: wreg[g][p] = (W[k0+2p], W[k0+2p+1])
    ull wreg[4][13];
    {
        const float* wb = d_wt + (size_t)(dir * H + jg) * G4;   // [g][k]
        int k0 = ks * SEG;
        #pragma unroll
        for (int g = 0; g < 4; g++) {
            #pragma unroll
            for (int p = 0; p < 13; p++) {
                float lo = wb[g * H + k0 + 2 * p];
                float hi = (2 * p + 1 < SEG) ? wb[g * H + k0 + 2 * p + 1] : 0.f;
                wreg[g][p] = packf2(lo, hi);
            }
        }
    }
    for (int i = tid; i < 2 * NBATCH * HROW; i += 400) ((float*)hbuf)[i] = 0.f;

    bool owner = (ks < NBATCH);
    int bg = grp * NBATCH + (ks & 3);
    int L = seq_len[bg];
    float ckeep = 0.f, hkeep = 0.f;
    int hseg = jg / SEG, hoff = jg % SEG;

    // prefetch gates for step 0
    float ngi = 0.f, ngf = 0.f, ngg = 0.f, ngo = 0.f;
    {
        int t0 = dir ? (T - 1) : 0;
        if (owner) {
            const float* gp = gates + ((size_t)bg * T + t0) * G4;
            ngi = gp[jg]; ngf = gp[H + jg]; ngg = gp[2 * H + jg]; ngo = gp[3 * H + jg];
        }
    }

    cluster_sync_();   // zeroed h visible cluster-wide

    for (int s = 0; s < T; s++) {
        int t = dir ? (T - 1 - s) : s;
        int cur = s & 1, nxt = cur ^ 1;
        float gi = ngi, gf = ngf, gg = ngg, go = ngo;

        float ai = 0.f, af = 0.f, ag = 0.f, ao = 0.f;
        #pragma unroll
        for (int b = 0; b < NBATCH; b++) {
            const float* hr = &hbuf[cur][b][ks * SEGP];
            ull a0 = 0, a1 = 0, a2 = 0, a3 = 0;
            #pragma unroll
            for (int q = 0; q < 6; q++) {
                ulonglong2 h2 = *(const ulonglong2*)(hr + 4 * q);
                a0 = ffma2(wreg[0][2 * q], h2.x, a0);
                a1 = ffma2(wreg[1][2 * q], h2.x, a1);
                a2 = ffma2(wreg[2][2 * q], h2.x, a2);
                a3 = ffma2(wreg[3][2 * q], h2.x, a3);
                a0 = ffma2(wreg[0][2 * q + 1], h2.y, a0);
                a1 = ffma2(wreg[1][2 * q + 1], h2.y, a1);
                a2 = ffma2(wreg[2][2 * q + 1], h2.y, a2);
                a3 = ffma2(wreg[3][2 * q + 1], h2.y, a3);
            }
            {
                ull hl = *(const ull*)(hr + 24);   // pair 12 (k 24, pad)
                a0 = ffma2(wreg[0][12], hl, a0);
                a1 = ffma2(wreg[1][12], hl, a1);
                a2 = ffma2(wreg[2][12], hl, a2);
                a3 = ffma2(wreg[3][12], hl, a3);
            }
            float2 v;
            v = uf2(a0); float r0 = v.x + v.y;
            v = uf2(a1); float r1 = v.x + v.y;
            v = uf2(a2); float r2 = v.x + v.y;
            v = uf2(a3); float r3 = v.x + v.y;
            #pragma unroll
            for (int o = 1; o < 8; o <<= 1) {
                r0 += __shfl_xor_sync(0xffffffffu, r0, o);
                r1 += __shfl_xor_sync(0xffffffffu, r1, o);
                r2 += __shfl_xor_sync(0xffffffffu, r2, o);
                r3 += __shfl_xor_sync(0xffffffffu, r3, o);
            }
            if (ks == b) { ai = r0; af = r1; ag = r2; ao = r3; }
        }

        if (owner) {
            float igt = fsigm(ai + gi);
            float fgt = fsigm(af + gf);
            float ogt = fsigm(ao + go);
            float cn = fgt * ckeep + igt * ftanh(ag + gg);
            float hn = ogt * ftanh(cn);
            bool m = (t < L);
            float hv = m ? hn : hkeep;
            ckeep = m ? cn : ckeep;
            hkeep = hv;

            uint32_t laddr = (uint32_t)__cvta_generic_to_shared(
                &hbuf[nxt][ks][hseg * SEGP + hoff]);
            st_shared_cluster(laddr, 0, hv);
            st_shared_cluster(laddr, 1, hv);
            st_shared_cluster(laddr, 2, hv);
            st_shared_cluster(laddr, 3, hv);

            hs[((size_t)bg * T + t) * H + jg] = hv;
        }

        cluster_arrive_();   // release our h stores
        // prefetch next step's gates while peers arrive
        if (s + 1 < T) {
            int t2 = dir ? (T - 2 - s) : (s + 1);
            if (owner) {
                const float* gp = gates + ((size_t)bg * T + t2) * G4;
                ngi = gp[jg]; ngf = gp[H + jg]; ngg = gp[2 * H + jg]; ngo = gp[3 * H + jg];
            }
        }
        cluster_wait_();
    }
}

// ---------------- 4) FC + log-softmax ----------------
#define FTOK 8
__global__ void fc_ls_kernel(const float* __restrict__ fcw, const float* __restrict__ fcb) {
    __shared__ float shw[2 * H * C];
    __shared__ float shh[FTOK][2 * H];
    __shared__ float sfeat[FTOK][C];
    __shared__ float slse[FTOK];

    int tid = threadIdx.x;
    int tt = tid / C;
    int c = tid % C;
    int tok0 = blockIdx.x * FTOK;

    for (int idx = tid; idx < 2 * H * C; idx += FTOK * C) {
        int cc = idx / (2 * H);
        int k = idx % (2 * H);
        shw[k * C + cc] = fcw[idx];
    }
    for (int idx = tid; idx < FTOK * 2 * H; idx += FTOK * C) {
        int t = idx / (2 * H);
        int k = idx % (2 * H);
        size_t tok = tok0 + t;
        shh[t][k] = (k < H) ? d_hf[tok * H + k] : d_hb[tok * H + (k - H)];
    }
    __syncthreads();

    float acc = fcb[c];
    const float* hrow = shh[tt];
    #pragma unroll 8
    for (int k = 0; k < 2 * H; k++)
        acc += hrow[k] * shw[k * C + c];
    sfeat[tt][c] = acc;
    __syncthreads();

    if (c == 0) {
        float m = sfeat[tt][0];
        #pragma unroll
        for (int i = 1; i < C; i++) m = fmaxf(m, sfeat[tt][i]);
        float ssum = 0.f;
        #pragma unroll
        for (int i = 0; i < C; i++) ssum += __expf(sfeat[tt][i] - m);
        slse[tt] = m + __logf(ssum);
    }
    __syncthreads();
    d_logits[(size_t)(tok0 + tt) * C + c] = acc - slse[tt];
}

// ---------------- 5) CRF NLL (one warp per batch) ----------------
__global__ void crf_kernel(const int* __restrict__ target,
                           const int* __restrict__ seq_len,
                           const float* __restrict__ trans,
                           const float* __restrict__ sv,
                           const float* __restrict__ ev) {
    int b = blockIdx.x;
    int tid = threadIdx.x;
    __shared__ float tr[C * C];
    __shared__ float alpha[C];

    for (int i = tid; i < C * C; i += 32) tr[i] = trans[i];
    int L = seq_len[b];
    const int* tgt = target + (size_t)b * T;
    const float* lg = d_logits + (size_t)b * T * C;

    float acc = 0.f;
    for (int t = tid; t < L; t += 32) acc += lg[(size_t)t * C + tgt[t]];
    for (int t = 1 + tid; t < L; t += 32) acc += trans[tgt[t - 1] * C + tgt[t]];
    #pragma unroll
    for (int o = 16; o > 0; o >>= 1) acc += __shfl_down_sync(0xffffffffu, acc, o);

    __syncwarp();
    if (tid < C) alpha[tid] = sv[tid] + lg[tid];
    __syncwarp();

    float trcol[C];
    if (tid < C) {
        #pragma unroll
        for (int c1 = 0; c1 < C; c1++) trcol[c1] = tr[c1 * C + tid];
    }

    for (int t = 1; t < L; t++) {
        float na = 0.f;
        if (tid < C) {
            float v[C];
            #pragma unroll
            for (int c1 = 0; c1 < C; c1++) v[c1] = alpha[c1] + trcol[c1];
            float mx[C];
            #pragma unroll
            for (int c1 = 0; c1 < C; c1++) mx[c1] = v[c1];
            #pragma unroll
            for (int st = 1; st < C; st *= 2)
                #pragma unroll
                for (int i = 0; i + st < C; i += 2 * st) mx[i] = fmaxf(mx[i], mx[i + st]);
            float m = mx[0];
            #pragma unroll
            for (int c1 = 0; c1 < C; c1++) v[c1] = __expf(v[c1] - m);
            #pragma unroll
            for (int st = 1; st < C; st *= 2)
                #pragma unroll
                for (int i = 0; i + st < C; i += 2 * st) v[i] += v[i + st];
            na = m + __logf(v[0]) + lg[(size_t)t * C + tid];
        }
        __syncwarp();
        if (tid < C) alpha[tid] = na;
        __syncwarp();
    }

    if (tid == 0) {
        float m = -1e30f;
        #pragma unroll
        for (int c = 0; c < C; c++) m = fmaxf(m, alpha[c] + ev[c]);
        float ssum = 0.f;
        #pragma unroll
        for (int c = 0; c < C; c++) ssum += __expf(alpha[c] + ev[c] - m);
        float logZ = m + __logf(ssum);
        float gold = acc + sv[tgt[0]] + ev[tgt[L - 1]];
        d_loss[b] = logZ - gold;
    }
}

// ---------------- 6) mean ----------------
__global__ void mean_kernel(float* __restrict__ out) {
    int tid = threadIdx.x;
    __shared__ float red[B];
    red[tid] = d_loss[tid];
    __syncthreads();
    #pragma unroll
    for (int s = 32; s > 0; s >>= 1) {
        if (tid < s) red[tid] += red[tid + s];
        __syncthreads();
    }
    if (tid == 0) out[0] = red[0] * (1.0f / B);
}

// ---------------- launch ----------------
extern "C" void kernel_launch(void* const* d_in, const int* in_sizes, int n_in,
                              void* d_out, int out_size) {
    const int* words    = (const int*)d_in[0];
    const int* seq_len  = (const int*)d_in[1];
    const int* target   = (const int*)d_in[2];
    const float* embed  = (const float*)d_in[3];
    const float* gamma  = (const float*)d_in[4];
    const float* beta   = (const float*)d_in[5];
    const float* wihf   = (const float*)d_in[6];
    const float* whhf   = (const float*)d_in[7];
    const float* bf     = (const float*)d_in[8];
    const float* wihb   = (const float*)d_in[9];
    const float* whhb   = (const float*)d_in[10];
    const float* bb     = (const float*)d_in[11];
    const float* fcw    = (const float*)d_in[12];
    const float* fcb    = (const float*)d_in[13];
    const float* trans  = (const float*)d_in[14];
    const float* sv     = (const float*)d_in[15];
    const float* ev     = (const float*)d_in[16];
    float* out = (float*)d_out;

    cudaFuncSetAttribute(gates_gemm,
                         cudaFuncAttributeMaxDynamicSharedMemorySize, GEMM_SMEM);

    transpose_whh<<<(2 * H * G4 + 255) / 256, 256>>>(whhf, whhb);

    embed_ln_kernel<<<B * T, 256>>>(words, embed, gamma, beta);

    dim3 ggrid((G4 + TBN - 1) / TBN, (B * T) / TBM, 2);
    gates_gemm<<<ggrid, 256, GEMM_SMEM>>>(wihf, bf, wihb, bb);

    lstm_cluster_kernel<<<128, 400>>>(seq_len);

    fc_ls_kernel<<<(B * T) / FTOK, FTOK * C>>>(fcw, fcb);

    crf_kernel<<<B, 32>>>(target, seq_len, trans, sv, ev);

    mean_kernel<<<1, B>>>(out);
}